// round 2
// baseline (speedup 1.0000x reference)
#include <cuda_runtime.h>
#include <math.h>

#define T_TOKENS 4096
#define HID 2560
#define NEXP 16
#define TOPK 6
#define TI 1536
#define VI 512
#define SI 3072
#define NPAIRS (T_TOKENS*TOPK)   /* 24576 */
#define NSLOTS 32

// ---------------- scratch (device globals; no runtime allocation) ----------
__device__ float g_hexp[(size_t)NPAIRS * TI];    // silu(g)*u per (token,expert) pair
__device__ float g_oexp[(size_t)NPAIRS * HID];   // weighted down-proj per pair
__device__ float g_hsh[(size_t)T_TOKENS * SI];   // shared expert hidden
__device__ float g_osh[(size_t)T_TOKENS * HID];  // shared expert output
__device__ int   g_slot_tok[NPAIRS];
__device__ float g_slot_w[NPAIRS];
__device__ int   g_pair_row[NPAIRS];
__device__ int   g_cnt[NSLOTS];
__device__ int   g_off[NSLOTS];
__device__ int   g_cur[NSLOTS];
__device__ int   g_tope[NPAIRS];
__device__ float g_topw[NPAIRS];

// ---------------- small kernels -------------------------------------------
__global__ void init_kernel() {
    if (threadIdx.x < NSLOTS) { g_cnt[threadIdx.x] = 0; g_cur[threadIdx.x] = 0; }
}

// One block per token: fp32 router, softmax, bias-corrected top-6, normalized weights.
__global__ void __launch_bounds__(128)
router_kernel(const float* __restrict__ x, const int* __restrict__ tt,
              const float* __restrict__ tw, const float* __restrict__ tb,
              const float* __restrict__ vw, const float* __restrict__ vb,
              float* __restrict__ out_logits)
{
    int t = blockIdx.x;
    int tid = threadIdx.x;
    bool vis = (tt[t] != 0);
    const float* w = vis ? vw : tw;
    const float* b = vis ? vb : tb;

    __shared__ float xs[HID];
    __shared__ float lg[NEXP];
    const float* xr = x + (size_t)t * HID;
    for (int i = tid; i < HID; i += 128) xs[i] = xr[i];
    __syncthreads();

    int e = tid >> 3;          // 16 groups of 8 threads, one expert each
    int l = tid & 7;
    const float* we = w + (size_t)e * HID;
    float s = 0.f;
    for (int k = l; k < HID; k += 8) s += xs[k] * we[k];
    for (int o = 4; o; o >>= 1) s += __shfl_down_sync(0xffffffffu, s, o);
    if (l == 0) lg[e] = s;
    __syncthreads();

    if (tid < NEXP) out_logits[(size_t)t * NEXP + tid] = lg[tid];

    if (tid == 0) {
        float mx = lg[0];
        for (int i = 1; i < NEXP; i++) mx = fmaxf(mx, lg[i]);
        float p[NEXP]; float sum = 0.f;
        for (int i = 0; i < NEXP; i++) { p[i] = expf(lg[i] - mx); sum += p[i]; }
        float inv = 1.f / sum;
        float corr[NEXP];
        for (int i = 0; i < NEXP; i++) { p[i] *= inv; corr[i] = p[i] + b[i]; }

        bool used[NEXP];
        for (int i = 0; i < NEXP; i++) used[i] = false;
        int   idxs[TOPK]; float ws[TOPK]; float wsum = 0.f;
        for (int j = 0; j < TOPK; j++) {
            int bi = -1; float bv = -1e30f;
            for (int i = 0; i < NEXP; i++)
                if (!used[i] && corr[i] > bv) { bv = corr[i]; bi = i; }
            used[bi] = true; idxs[j] = bi; ws[j] = p[bi]; wsum += p[bi];
        }
        float invw = 1.f / fmaxf(wsum, 1e-12f);
        int mbase = vis ? 16 : 0;
        for (int j = 0; j < TOPK; j++) {
            g_tope[t*TOPK + j] = mbase + idxs[j];
            g_topw[t*TOPK + j] = ws[j] * invw;
            atomicAdd(&g_cnt[mbase + idxs[j]], 1);
        }
    }
}

__global__ void scan_kernel() {
    if (threadIdx.x == 0) {
        int acc = 0;
        for (int i = 0; i < NSLOTS; i++) { g_off[i] = acc; acc += g_cnt[i]; }
    }
}

__global__ void scatter_kernel() {
    int p = blockIdx.x * blockDim.x + threadIdx.x;
    if (p >= NPAIRS) return;
    int slot = g_tope[p];
    int pos = atomicAdd(&g_cur[slot], 1);
    int g = g_off[slot] + pos;
    g_slot_tok[g] = p / TOPK;
    g_slot_w[g]   = g_topw[p];
    g_pair_row[p] = g;
}

// ---------------- fused gate/up GEMM + SiLU --------------------------------
// BM=128, BN=64, BK=16, 256 threads, per-thread 8x4 x two accumulators.
// mode 0: text experts, 1: vis experts, 2: shared expert.
__global__ void __launch_bounds__(256)
gateup_kernel(const float* __restrict__ X, const float* __restrict__ Wb,
              const float* __restrict__ Wu2, int mode)
{
    int I, ldw, M, baserow;
    const float *Wg, *Wu;
    float* outp; int ldo;
    if (mode == 0) {
        int s = blockIdx.z;
        I = TI; ldw = 2*TI;
        Wg = Wb + (size_t)s * HID * (2*TI); Wu = Wg + TI;
        M = g_cnt[s]; baserow = g_off[s];
        outp = g_hexp; ldo = TI;
    } else if (mode == 1) {
        int s = blockIdx.z;
        I = VI; ldw = 2*VI;
        Wg = Wb + (size_t)s * HID * (2*VI); Wu = Wg + VI;
        M = g_cnt[16+s]; baserow = g_off[16+s];
        outp = g_hexp; ldo = TI;
    } else {
        I = SI; ldw = SI;
        Wg = Wb; Wu = Wu2;
        M = T_TOKENS; baserow = 0;
        outp = g_hsh; ldo = SI;
    }
    int m0 = blockIdx.y * 128;
    int n0 = blockIdx.x * 64;
    if (m0 >= M || n0 >= I) return;

    __shared__ float As[16][132];
    __shared__ float Bg[16][68];
    __shared__ float Bu[16][68];

    int tid = threadIdx.x;
    int ar = tid >> 2;           // 0..63
    int ac = (tid & 3) << 2;     // 0,4,8,12
    int br = tid >> 4;           // 0..15
    int bc = (tid & 15) << 2;    // 0..60
    int ty = tid >> 4;           // 0..15
    int tx = tid & 15;           // 0..15

    int r0 = min(m0 + ar, M - 1);
    int r1 = min(m0 + 64 + ar, M - 1);
    int tok0 = (mode < 2) ? g_slot_tok[baserow + r0] : r0;
    int tok1 = (mode < 2) ? g_slot_tok[baserow + r1] : r1;
    const float* a0p = X + (size_t)tok0 * HID + ac;
    const float* a1p = X + (size_t)tok1 * HID + ac;
    const float* bgp = Wg + (size_t)br * ldw + n0 + bc;
    const float* bup = Wu + (size_t)br * ldw + n0 + bc;

    float accg[8][4], accu[8][4];
    #pragma unroll
    for (int i = 0; i < 8; i++)
        #pragma unroll
        for (int j = 0; j < 4; j++) { accg[i][j] = 0.f; accu[i][j] = 0.f; }

    for (int k0 = 0; k0 < HID; k0 += 16) {
        float4 a0 = *(const float4*)(a0p + k0);
        float4 a1 = *(const float4*)(a1p + k0);
        float4 bg = *(const float4*)(bgp + (size_t)k0 * ldw);
        float4 bu = *(const float4*)(bup + (size_t)k0 * ldw);
        As[ac+0][ar] = a0.x; As[ac+1][ar] = a0.y; As[ac+2][ar] = a0.z; As[ac+3][ar] = a0.w;
        As[ac+0][64+ar] = a1.x; As[ac+1][64+ar] = a1.y; As[ac+2][64+ar] = a1.z; As[ac+3][64+ar] = a1.w;
        *(float4*)&Bg[br][bc] = bg;
        *(float4*)&Bu[br][bc] = bu;
        __syncthreads();
        #pragma unroll
        for (int k = 0; k < 16; k++) {
            float a[8], bgv[4], buv[4];
            #pragma unroll
            for (int i = 0; i < 8; i++) a[i] = As[k][ty*8 + i];
            #pragma unroll
            for (int j = 0; j < 4; j++) { bgv[j] = Bg[k][tx*4 + j]; buv[j] = Bu[k][tx*4 + j]; }
            #pragma unroll
            for (int i = 0; i < 8; i++)
                #pragma unroll
                for (int j = 0; j < 4; j++) {
                    accg[i][j] += a[i] * bgv[j];
                    accu[i][j] += a[i] * buv[j];
                }
        }
        __syncthreads();
    }

    #pragma unroll
    for (int i = 0; i < 8; i++) {
        int m = m0 + ty*8 + i;
        if (m >= M) continue;
        #pragma unroll
        for (int j = 0; j < 4; j++) {
            int n = n0 + tx*4 + j;
            float g = accg[i][j];
            float h = (g / (1.f + expf(-g))) * accu[i][j];
            outp[(size_t)(baserow + m) * ldo + n] = h;
        }
    }
}

// ---------------- down-proj GEMM (+ per-row routing weight) ----------------
// BM=128, BN=128, BK=16, 256 threads, per-thread 8x8.
__global__ void __launch_bounds__(256)
down_kernel(const float* __restrict__ Wb, int mode)
{
    int I, M, baserow;
    const float* Wd;
    const float* A; int lda;
    float* outp; bool scl;
    if (mode == 0) {
        int s = blockIdx.z;
        I = TI; Wd = Wb + (size_t)s * TI * HID;
        M = g_cnt[s]; baserow = g_off[s];
        A = g_hexp; lda = TI; outp = g_oexp; scl = true;
    } else if (mode == 1) {
        int s = blockIdx.z;
        I = VI; Wd = Wb + (size_t)s * VI * HID;
        M = g_cnt[16+s]; baserow = g_off[16+s];
        A = g_hexp; lda = TI; outp = g_oexp; scl = true;
    } else {
        I = SI; Wd = Wb;
        M = T_TOKENS; baserow = 0;
        A = g_hsh; lda = SI; outp = g_osh; scl = false;
    }
    int m0 = blockIdx.y * 128, n0 = blockIdx.x * 128;
    if (m0 >= M) return;

    __shared__ float As[16][132];
    __shared__ float Bs[16][132];

    int tid = threadIdx.x;
    int ar = tid >> 2, ac = (tid & 3) << 2;
    int br = tid >> 5, bc = (tid & 31) << 2;
    int ty = tid >> 4, tx = tid & 15;

    int r0 = min(m0 + ar, M - 1), r1 = min(m0 + 64 + ar, M - 1);
    const float* a0p = A + (size_t)(baserow + r0) * lda + ac;
    const float* a1p = A + (size_t)(baserow + r1) * lda + ac;
    const float* b0p = Wd + (size_t)br * HID + n0 + bc;
    const float* b1p = Wd + (size_t)(br + 8) * HID + n0 + bc;

    float acc[8][8];
    #pragma unroll
    for (int i = 0; i < 8; i++)
        #pragma unroll
        for (int j = 0; j < 8; j++) acc[i][j] = 0.f;

    for (int k0 = 0; k0 < I; k0 += 16) {
        float4 a0 = *(const float4*)(a0p + k0);
        float4 a1 = *(const float4*)(a1p + k0);
        float4 b0 = *(const float4*)(b0p + (size_t)k0 * HID);
        float4 b1 = *(const float4*)(b1p + (size_t)k0 * HID);
        As[ac+0][ar] = a0.x; As[ac+1][ar] = a0.y; As[ac+2][ar] = a0.z; As[ac+3][ar] = a0.w;
        As[ac+0][64+ar] = a1.x; As[ac+1][64+ar] = a1.y; As[ac+2][64+ar] = a1.z; As[ac+3][64+ar] = a1.w;
        *(float4*)&Bs[br][bc]   = b0;
        *(float4*)&Bs[br+8][bc] = b1;
        __syncthreads();
        #pragma unroll
        for (int k = 0; k < 16; k++) {
            float a[8], b[8];
            #pragma unroll
            for (int i = 0; i < 8; i++) a[i] = As[k][ty*8 + i];
            #pragma unroll
            for (int j = 0; j < 8; j++) b[j] = Bs[k][tx*8 + j];
            #pragma unroll
            for (int i = 0; i < 8; i++)
                #pragma unroll
                for (int j = 0; j < 8; j++) acc[i][j] += a[i] * b[j];
        }
        __syncthreads();
    }

    #pragma unroll
    for (int i = 0; i < 8; i++) {
        int m = m0 + ty*8 + i;
        if (m >= M) continue;
        float w = scl ? g_slot_w[baserow + m] : 1.f;
        #pragma unroll
        for (int j = 0; j < 8; j++)
            outp[(size_t)(baserow + m) * HID + n0 + tx*8 + j] = acc[i][j] * w;
    }
}

// ---------------- finalize: gather 6 expert rows + shared ------------------
__global__ void __launch_bounds__(256)
finalize_kernel(float* __restrict__ out)
{
    int t = blockIdx.y;
    int h = blockIdx.x * 256 + threadIdx.x;
    float s = g_osh[(size_t)t * HID + h];
    #pragma unroll
    for (int j = 0; j < TOPK; j++) {
        int g = g_pair_row[t*TOPK + j];
        s += g_oexp[(size_t)g * HID + h];
    }
    out[(size_t)t * HID + h] = s;
}

// ---------------- launch ----------------------------------------------------
extern "C" void kernel_launch(void* const* d_in, const int* in_sizes, int n_in,
                              void* d_out, int out_size)
{
    (void)in_sizes; (void)n_in; (void)out_size;
    const float* x   = (const float*)d_in[0];
    const int*   tt  = (const int*)  d_in[1];
    const float* trw = (const float*)d_in[2];
    const float* trb = (const float*)d_in[3];
    const float* tgu = (const float*)d_in[4];
    const float* tdn = (const float*)d_in[5];
    const float* vrw = (const float*)d_in[6];
    const float* vrb = (const float*)d_in[7];
    const float* vgu = (const float*)d_in[8];
    const float* vdn = (const float*)d_in[9];
    const float* sg  = (const float*)d_in[10];
    const float* su  = (const float*)d_in[11];
    const float* sd  = (const float*)d_in[12];
    float* out        = (float*)d_out;
    float* out_logits = out + (size_t)T_TOKENS * HID;

    init_kernel<<<1, 32>>>();
    router_kernel<<<T_TOKENS, 128>>>(x, tt, trw, trb, vrw, vrb, out_logits);
    scan_kernel<<<1, 1>>>();
    scatter_kernel<<<NPAIRS/256, 256>>>();

    gateup_kernel<<<dim3(TI/64, 32, 16), 256>>>(x, tgu, nullptr, 0);
    gateup_kernel<<<dim3(VI/64, 32, 16), 256>>>(x, vgu, nullptr, 1);
    gateup_kernel<<<dim3(SI/64, T_TOKENS/128, 1), 256>>>(x, sg, su, 2);

    down_kernel<<<dim3(HID/128, 32, 16), 256>>>(tdn, 0);
    down_kernel<<<dim3(HID/128, 32, 16), 256>>>(vdn, 1);
    down_kernel<<<dim3(HID/128, T_TOKENS/128, 1), 256>>>(sd, 2);

    finalize_kernel<<<dim3(HID/256, T_TOKENS), 256>>>(out);
}

// round 10
// speedup vs baseline: 1.7641x; 1.7641x over previous
#include <cuda_runtime.h>
#include <cuda_bf16.h>
#include <math.h>
#include <stdint.h>

#define T_TOKENS 4096
#define HID 2560
#define NEXP 16
#define TOPK 6
#define TI 1536
#define VI 512
#define SI 3072
#define NPAIRS (T_TOKENS*TOPK)   /* 24576 */
#define NSLOTS 32

// ---------------- scratch (device globals; no runtime allocation) ----------
__device__ float g_cgu[(size_t)NPAIRS * (2*TI)];   // gate_up GEMM out (experts)
__device__ float g_csh[(size_t)T_TOKENS * (2*SI)]; // gate/up GEMM out (shared)
__device__ float g_hexp[(size_t)NPAIRS * TI];      // silu(g)*u per pair
__device__ float g_hsh[(size_t)T_TOKENS * SI];     // silu(g)*u shared
__device__ float g_oexp[(size_t)NPAIRS * HID];     // weighted down out per pair
__device__ float g_osh[(size_t)T_TOKENS * HID];    // shared down out
__device__ int   g_slot_tok[NPAIRS];
__device__ float g_slot_w[NPAIRS];
__device__ int   g_pair_row[NPAIRS];
__device__ int   g_cnt[NSLOTS];
__device__ int   g_off[NSLOTS];
__device__ int   g_cur[NSLOTS];
__device__ int   g_tope[NPAIRS];
__device__ float g_topw[NPAIRS];

// ---------------- helpers ---------------------------------------------------
__device__ __forceinline__ uint32_t smem_u32(const void* p) {
    return (uint32_t)__cvta_generic_to_shared(p);
}

#define LDSM4(R0,R1,R2,R3,A) \
    asm volatile("ldmatrix.sync.aligned.m8n8.x4.shared.b16 {%0,%1,%2,%3}, [%4];" \
        : "=r"(R0), "=r"(R1), "=r"(R2), "=r"(R3) : "r"(A))
#define LDSM4T(R0,R1,R2,R3,A) \
    asm volatile("ldmatrix.sync.aligned.m8n8.x4.trans.shared.b16 {%0,%1,%2,%3}, [%4];" \
        : "=r"(R0), "=r"(R1), "=r"(R2), "=r"(R3) : "r"(A))
#define MMA(D,A0,A1,A2,A3,B0,B1) \
    asm volatile("mma.sync.aligned.m16n8k16.row.col.f32.bf16.bf16.f32 " \
        "{%0,%1,%2,%3}, {%4,%5,%6,%7}, {%8,%9}, {%0,%1,%2,%3};" \
        : "+f"((D)[0]), "+f"((D)[1]), "+f"((D)[2]), "+f"((D)[3]) \
        : "r"(A0), "r"(A1), "r"(A2), "r"(A3), "r"(B0), "r"(B1))

// split float4 into packed bf16 hi pairs and bf16 residual-lo pairs
__device__ __forceinline__ void split4(const float4& v, uint2& hi, uint2& lo) {
    uint32_t h01, h23, l01, l23;
    asm("cvt.rn.bf16x2.f32 %0, %1, %2;" : "=r"(h01) : "f"(v.y), "f"(v.x));
    asm("cvt.rn.bf16x2.f32 %0, %1, %2;" : "=r"(h23) : "f"(v.w), "f"(v.z));
    float f0 = __uint_as_float(h01 << 16);
    float f1 = __uint_as_float(h01 & 0xffff0000u);
    float f2 = __uint_as_float(h23 << 16);
    float f3 = __uint_as_float(h23 & 0xffff0000u);
    float r0 = v.x - f0, r1 = v.y - f1, r2 = v.z - f2, r3 = v.w - f3;
    asm("cvt.rn.bf16x2.f32 %0, %1, %2;" : "=r"(l01) : "f"(r1), "f"(r0));
    asm("cvt.rn.bf16x2.f32 %0, %1, %2;" : "=r"(l23) : "f"(r3), "f"(r2));
    hi = make_uint2(h01, h23); lo = make_uint2(l01, l23);
}

// ---------------- small kernels -------------------------------------------
__global__ void init_kernel() {
    if (threadIdx.x < NSLOTS) { g_cnt[threadIdx.x] = 0; g_cur[threadIdx.x] = 0; }
}

__global__ void __launch_bounds__(128)
router_kernel(const float* __restrict__ x, const int* __restrict__ tt,
              const float* __restrict__ tw, const float* __restrict__ tb,
              const float* __restrict__ vw, const float* __restrict__ vb,
              float* __restrict__ out_logits)
{
    int t = blockIdx.x;
    int tid = threadIdx.x;
    bool vis = (tt[t] != 0);
    const float* w = vis ? vw : tw;
    const float* b = vis ? vb : tb;

    __shared__ float xs[HID];
    __shared__ float lg[NEXP];
    const float* xr = x + (size_t)t * HID;
    for (int i = tid; i < HID; i += 128) xs[i] = xr[i];
    __syncthreads();

    int e = tid >> 3;
    int l = tid & 7;
    const float* we = w + (size_t)e * HID;
    float s = 0.f;
    for (int k = l; k < HID; k += 8) s += xs[k] * we[k];
    for (int o = 4; o; o >>= 1) s += __shfl_down_sync(0xffffffffu, s, o);
    if (l == 0) lg[e] = s;
    __syncthreads();

    if (tid < NEXP) out_logits[(size_t)t * NEXP + tid] = lg[tid];

    if (tid == 0) {
        float mx = lg[0];
        for (int i = 1; i < NEXP; i++) mx = fmaxf(mx, lg[i]);
        float p[NEXP]; float sum = 0.f;
        for (int i = 0; i < NEXP; i++) { p[i] = expf(lg[i] - mx); sum += p[i]; }
        float inv = 1.f / sum;
        float corr[NEXP];
        for (int i = 0; i < NEXP; i++) { p[i] *= inv; corr[i] = p[i] + b[i]; }

        bool used[NEXP];
        for (int i = 0; i < NEXP; i++) used[i] = false;
        int idxs[TOPK]; float ws[TOPK]; float wsum = 0.f;
        for (int j = 0; j < TOPK; j++) {
            int bi = -1; float bv = -1e30f;
            for (int i = 0; i < NEXP; i++)
                if (!used[i] && corr[i] > bv) { bv = corr[i]; bi = i; }
            used[bi] = true; idxs[j] = bi; ws[j] = p[bi]; wsum += p[bi];
        }
        float invw = 1.f / fmaxf(wsum, 1e-12f);
        int mbase = vis ? 16 : 0;
        for (int j = 0; j < TOPK; j++) {
            g_tope[t*TOPK + j] = mbase + idxs[j];
            g_topw[t*TOPK + j] = ws[j] * invw;
            atomicAdd(&g_cnt[mbase + idxs[j]], 1);
        }
    }
}

__global__ void scan_kernel() {
    if (threadIdx.x == 0) {
        int acc = 0;
        for (int i = 0; i < NSLOTS; i++) { g_off[i] = acc; acc += g_cnt[i]; }
    }
}

__global__ void scatter_kernel() {
    int p = blockIdx.x * blockDim.x + threadIdx.x;
    if (p >= NPAIRS) return;
    int slot = g_tope[p];
    int pos = atomicAdd(&g_cur[slot], 1);
    int g = g_off[slot] + pos;
    g_slot_tok[g] = p / TOPK;
    g_slot_w[g]   = g_topw[p];
    g_pair_row[p] = g;
}

// ---------------- bf16x3 split-precision tensor-core GEMM ------------------
// C[M,N] = A[M,K] @ B_e[K,N]; B_e = B + blockIdx.z * bstride  (per-expert slab)
// BM=128, BN=128, BK=32. 8 warps: 4 (M) x 2 (N), warp tile 32x64.
// mode: 0 = A rows gathered via g_slot_tok; 1 = A rows contiguous at baserow;
//       2 = dense (M = T_TOKENS)
#define STG_AH 0
#define STG_AL 10240
#define STG_BH 20480
#define STG_BL 29184
#define STG_SZ 37888

__global__ void __launch_bounds__(256)
gemm_bf16x3(const float* __restrict__ Xp, const float* __restrict__ B,
            size_t bstride, int lda, int ldb, int ldc, int K,
            int mode, int slotbase, int scale, int abuf, int cbuf, int coloff)
{
    __shared__ __align__(16) char S[STG_SZ];

    int M, baserow;
    if (mode == 2) { M = T_TOKENS; baserow = 0; }
    else { int s = slotbase + blockIdx.z; M = g_cnt[s]; baserow = g_off[s]; }
    int m0 = blockIdx.x * 128;
    if (m0 >= M) return;
    int n0 = blockIdx.y * 128;

    B += (size_t)blockIdx.z * bstride;    // per-expert weight slab

    const float* Abase = (abuf == 0) ? Xp : (abuf == 1) ? g_hexp : g_hsh;
    float* Cb = ((cbuf == 0) ? g_cgu : (cbuf == 1) ? g_csh :
                 (cbuf == 2) ? g_oexp : g_osh) + coloff;

    int tid = threadIdx.x, lane = tid & 31, wid = tid >> 5;
    int wm = wid & 3, wn = wid >> 2;

    // A loader: 2 threads per row, 16 cols each
    int arow = tid >> 1, ak = (tid & 1) * 16;
    int rr = min(m0 + arow, M - 1);
    const float* Aptr;
    if (mode == 0) Aptr = Abase + (size_t)g_slot_tok[baserow + rr] * lda + ak;
    else           Aptr = Abase + (size_t)(baserow + rr) * lda + ak;

    // B loader: 8 threads per k-row, 16 cols each
    int bk = tid >> 3, bn = (tid & 7) * 16;
    const float* Bp = B + n0 + bn;

    float acc[2][8][4];
    #pragma unroll
    for (int i = 0; i < 2; i++)
        #pragma unroll
        for (int j = 0; j < 8; j++)
            #pragma unroll
            for (int q = 0; q < 4; q++) acc[i][j][q] = 0.f;

    float4 pa[4], pb[4];
    #pragma unroll
    for (int q = 0; q < 4; q++) {
        pa[q] = *(const float4*)(Aptr + q*4);
        pb[q] = *(const float4*)(Bp + (size_t)bk * ldb + q*4);
    }

    uint32_t sbase = smem_u32(S);
    uint32_t aoff = (uint32_t)arow*80u + (uint32_t)ak*2u;
    uint32_t boff = (uint32_t)bk*272u + (uint32_t)bn*2u;

    const int NCH = K / 32;
    for (int c = 0; c < NCH; c++) {
        // convert + store current chunk
        #pragma unroll
        for (int q = 0; q < 4; q++) {
            uint2 hi, lo;
            split4(pa[q], hi, lo);
            *(uint2*)(S + STG_AH + aoff + q*8) = hi;
            *(uint2*)(S + STG_AL + aoff + q*8) = lo;
            split4(pb[q], hi, lo);
            *(uint2*)(S + STG_BH + boff + q*8) = hi;
            *(uint2*)(S + STG_BL + boff + q*8) = lo;
        }
        __syncthreads();
        // prefetch next chunk (overlaps with compute)
        if (c + 1 < NCH) {
            int k0 = (c + 1) * 32;
            #pragma unroll
            for (int q = 0; q < 4; q++) {
                pa[q] = *(const float4*)(Aptr + k0 + q*4);
                pb[q] = *(const float4*)(Bp + (size_t)(k0 + bk) * ldb + q*4);
            }
        }
        // compute 2 k16 steps
        #pragma unroll
        for (int ks = 0; ks < 2; ks++) {
            uint32_t ah[2][4], al[2][4], bh[8][2], bl[8][2];
            #pragma unroll
            for (int mi = 0; mi < 2; mi++) {
                uint32_t ra = (uint32_t)(wm*32 + mi*16 + (lane & 15)) * 80u
                            + (uint32_t)(ks*32) + (uint32_t)((lane >> 4) * 16);
                LDSM4(ah[mi][0], ah[mi][1], ah[mi][2], ah[mi][3], sbase + STG_AH + ra);
                LDSM4(al[mi][0], al[mi][1], al[mi][2], al[mi][3], sbase + STG_AL + ra);
            }
            #pragma unroll
            for (int p = 0; p < 4; p++) {
                uint32_t rb = (uint32_t)(ks*16 + (lane & 15)) * 272u
                            + (uint32_t)((wn*64 + p*16 + ((lane >> 4) * 8)) * 2);
                LDSM4T(bh[2*p][0], bh[2*p][1], bh[2*p+1][0], bh[2*p+1][1], sbase + STG_BH + rb);
                LDSM4T(bl[2*p][0], bl[2*p][1], bl[2*p+1][0], bl[2*p+1][1], sbase + STG_BL + rb);
            }
            #pragma unroll
            for (int mi = 0; mi < 2; mi++)
                #pragma unroll
                for (int nj = 0; nj < 8; nj++) {
                    MMA(acc[mi][nj], ah[mi][0], ah[mi][1], ah[mi][2], ah[mi][3],
                        bh[nj][0], bh[nj][1]);
                    MMA(acc[mi][nj], ah[mi][0], ah[mi][1], ah[mi][2], ah[mi][3],
                        bl[nj][0], bl[nj][1]);
                    MMA(acc[mi][nj], al[mi][0], al[mi][1], al[mi][2], al[mi][3],
                        bh[nj][0], bh[nj][1]);
                }
        }
        __syncthreads();
    }

    // epilogue
    #pragma unroll
    for (int mi = 0; mi < 2; mi++) {
        int row0 = m0 + wm*32 + mi*16 + (lane >> 2);
        int row1 = row0 + 8;
        float w0 = 1.f, w1 = 1.f;
        if (scale) {
            if (row0 < M) w0 = g_slot_w[baserow + row0];
            if (row1 < M) w1 = g_slot_w[baserow + row1];
        }
        #pragma unroll
        for (int nj = 0; nj < 8; nj++) {
            int col = n0 + wn*64 + nj*8 + (lane & 3)*2;
            if (row0 < M) {
                float2 v = make_float2(acc[mi][nj][0]*w0, acc[mi][nj][1]*w0);
                *(float2*)(Cb + (size_t)(baserow + row0)*ldc + col) = v;
            }
            if (row1 < M) {
                float2 v = make_float2(acc[mi][nj][2]*w1, acc[mi][nj][3]*w1);
                *(float2*)(Cb + (size_t)(baserow + row1)*ldc + col) = v;
            }
        }
    }
}

// ---------------- elementwise SiLU * up ------------------------------------
__global__ void __launch_bounds__(256)
silu_experts()
{
    int row = blockIdx.y;
    int i = blockIdx.x * 256 + threadIdx.x;
    int boundary = g_off[16];               // first vis row
    int I = (row < boundary) ? TI : VI;
    if (i >= I) return;
    const float* crow = g_cgu + (size_t)row * (2*TI);
    float g = crow[i], u = crow[I + i];
    g_hexp[(size_t)row * TI + i] = g / (1.f + expf(-g)) * u;
}

__global__ void __launch_bounds__(256)
silu_shared()
{
    int row = blockIdx.y;
    int i = blockIdx.x * 256 + threadIdx.x;
    const float* crow = g_csh + (size_t)row * (2*SI);
    float g = crow[i], u = crow[SI + i];
    g_hsh[(size_t)row * SI + i] = g / (1.f + expf(-g)) * u;
}

// ---------------- finalize: gather 6 expert rows + shared ------------------
__global__ void __launch_bounds__(256)
finalize_kernel(float* __restrict__ out)
{
    int t = blockIdx.y;
    int h = blockIdx.x * 256 + threadIdx.x;
    float s = g_osh[(size_t)t * HID + h];
    #pragma unroll
    for (int j = 0; j < TOPK; j++) {
        int g = g_pair_row[t*TOPK + j];
        s += g_oexp[(size_t)g * HID + h];
    }
    out[(size_t)t * HID + h] = s;
}

// ---------------- launch ----------------------------------------------------
extern "C" void kernel_launch(void* const* d_in, const int* in_sizes, int n_in,
                              void* d_out, int out_size)
{
    (void)in_sizes; (void)n_in; (void)out_size;
    const float* x   = (const float*)d_in[0];
    const int*   tt  = (const int*)  d_in[1];
    const float* trw = (const float*)d_in[2];
    const float* trb = (const float*)d_in[3];
    const float* tgu = (const float*)d_in[4];
    const float* tdn = (const float*)d_in[5];
    const float* vrw = (const float*)d_in[6];
    const float* vrb = (const float*)d_in[7];
    const float* vgu = (const float*)d_in[8];
    const float* vdn = (const float*)d_in[9];
    const float* sg  = (const float*)d_in[10];
    const float* su  = (const float*)d_in[11];
    const float* sd  = (const float*)d_in[12];
    float* out        = (float*)d_out;
    float* out_logits = out + (size_t)T_TOKENS * HID;

    init_kernel<<<1, 32>>>();
    router_kernel<<<T_TOKENS, 128>>>(x, tt, trw, trb, vrw, vrb, out_logits);
    scan_kernel<<<1, 1>>>();
    scatter_kernel<<<NPAIRS/256, 256>>>();

    // gate/up GEMMs (Mblocks in x so same-N CTAs run together -> L2 B reuse)
    gemm_bf16x3<<<dim3(32, (2*TI)/128, 16), 256>>>(x, tgu, (size_t)HID*2*TI, HID, 2*TI, 2*TI, HID, 0, 0,  0, 0, 0, 0);
    gemm_bf16x3<<<dim3(32, (2*VI)/128, 16), 256>>>(x, vgu, (size_t)HID*2*VI, HID, 2*VI, 2*TI, HID, 0, 16, 0, 0, 0, 0);
    gemm_bf16x3<<<dim3(32, SI/128, 1),      256>>>(x, sg,  0,                HID, SI,   2*SI, HID, 2, 0,  0, 0, 1, 0);
    gemm_bf16x3<<<dim3(32, SI/128, 1),      256>>>(x, su,  0,                HID, SI,   2*SI, HID, 2, 0,  0, 0, 1, SI);

    silu_experts<<<dim3(TI/256, NPAIRS), 256>>>();
    silu_shared<<<dim3(SI/256, T_TOKENS), 256>>>();

    // down GEMMs
    gemm_bf16x3<<<dim3(32, HID/128, 16), 256>>>(x, tdn, (size_t)TI*HID, TI, HID, HID, TI, 1, 0,  1, 1, 2, 0);
    gemm_bf16x3<<<dim3(32, HID/128, 16), 256>>>(x, vdn, (size_t)VI*HID, TI, HID, HID, VI, 1, 16, 1, 1, 2, 0);
    gemm_bf16x3<<<dim3(32, HID/128, 1),  256>>>(x, sd,  0,              SI, HID, HID, SI, 2, 0,  0, 2, 3, 0);

    finalize_kernel<<<dim3(HID/256, T_TOKENS), 256>>>(out);
}

// round 13
// speedup vs baseline: 1.8816x; 1.0666x over previous
#include <cuda_runtime.h>
#include <cuda_bf16.h>
#include <math.h>
#include <stdint.h>

#define T_TOKENS 4096
#define HID 2560
#define NEXP 16
#define TOPK 6
#define TI 1536
#define VI 512
#define SI 3072
#define NPAIRS (T_TOKENS*TOPK)   /* 24576 */
#define NSLOTS 32

// ---------------- scratch (device globals; no runtime allocation) ----------
__device__ float g_cgu[(size_t)NPAIRS * (2*TI)];   // gate_up GEMM out (experts)
__device__ float g_csh[(size_t)T_TOKENS * (2*SI)]; // gate/up GEMM out (shared)
__device__ float g_oexp[(size_t)NPAIRS * HID];     // weighted down out per pair
__device__ float g_osh[(size_t)T_TOKENS * HID];    // shared down out

// pre-split bf16 hi/lo planes
__device__ __nv_bfloat16 g_xh[(size_t)T_TOKENS*HID],      g_xl[(size_t)T_TOKENS*HID];
__device__ __nv_bfloat16 g_tguh[(size_t)NEXP*HID*2*TI],   g_tgul[(size_t)NEXP*HID*2*TI];
__device__ __nv_bfloat16 g_tdnh[(size_t)NEXP*TI*HID],     g_tdnl[(size_t)NEXP*TI*HID];
__device__ __nv_bfloat16 g_vguh[(size_t)NEXP*HID*2*VI],   g_vgul[(size_t)NEXP*HID*2*VI];
__device__ __nv_bfloat16 g_vdnh[(size_t)NEXP*VI*HID],     g_vdnl[(size_t)NEXP*VI*HID];
__device__ __nv_bfloat16 g_sgh[(size_t)HID*SI],           g_sgl[(size_t)HID*SI];
__device__ __nv_bfloat16 g_suh[(size_t)HID*SI],           g_sul[(size_t)HID*SI];
__device__ __nv_bfloat16 g_sdh[(size_t)SI*HID],           g_sdl[(size_t)SI*HID];
__device__ __nv_bfloat16 g_hexph[(size_t)NPAIRS*TI],      g_hexpl[(size_t)NPAIRS*TI];
__device__ __nv_bfloat16 g_hshh[(size_t)T_TOKENS*SI],     g_hshl[(size_t)T_TOKENS*SI];

__device__ int   g_slot_tok[NPAIRS];
__device__ float g_slot_w[NPAIRS];
__device__ int   g_pair_row[NPAIRS];
__device__ int   g_cnt[NSLOTS];
__device__ int   g_off[NSLOTS];
__device__ int   g_cur[NSLOTS];
__device__ int   g_tope[NPAIRS];
__device__ float g_topw[NPAIRS];

// ---------------- helpers ---------------------------------------------------
__device__ __forceinline__ uint32_t smem_u32(const void* p) {
    return (uint32_t)__cvta_generic_to_shared(p);
}

#define LDSM4(R0,R1,R2,R3,A) \
    asm volatile("ldmatrix.sync.aligned.m8n8.x4.shared.b16 {%0,%1,%2,%3}, [%4];" \
        : "=r"(R0), "=r"(R1), "=r"(R2), "=r"(R3) : "r"(A))
#define LDSM4T(R0,R1,R2,R3,A) \
    asm volatile("ldmatrix.sync.aligned.m8n8.x4.trans.shared.b16 {%0,%1,%2,%3}, [%4];" \
        : "=r"(R0), "=r"(R1), "=r"(R2), "=r"(R3) : "r"(A))
#define MMA(D,A0,A1,A2,A3,B0,B1) \
    asm volatile("mma.sync.aligned.m16n8k16.row.col.f32.bf16.bf16.f32 " \
        "{%0,%1,%2,%3}, {%4,%5,%6,%7}, {%8,%9}, {%0,%1,%2,%3};" \
        : "+f"((D)[0]), "+f"((D)[1]), "+f"((D)[2]), "+f"((D)[3]) \
        : "r"(A0), "r"(A1), "r"(A2), "r"(A3), "r"(B0), "r"(B1))

// split float4 into packed bf16 hi pairs and bf16 residual-lo pairs
__device__ __forceinline__ void split4(const float4& v, uint2& hi, uint2& lo) {
    uint32_t h01, h23, l01, l23;
    asm("cvt.rn.bf16x2.f32 %0, %1, %2;" : "=r"(h01) : "f"(v.y), "f"(v.x));
    asm("cvt.rn.bf16x2.f32 %0, %1, %2;" : "=r"(h23) : "f"(v.w), "f"(v.z));
    float f0 = __uint_as_float(h01 << 16);
    float f1 = __uint_as_float(h01 & 0xffff0000u);
    float f2 = __uint_as_float(h23 << 16);
    float f3 = __uint_as_float(h23 & 0xffff0000u);
    float r0 = v.x - f0, r1 = v.y - f1, r2 = v.z - f2, r3 = v.w - f3;
    asm("cvt.rn.bf16x2.f32 %0, %1, %2;" : "=r"(l01) : "f"(r1), "f"(r0));
    asm("cvt.rn.bf16x2.f32 %0, %1, %2;" : "=r"(l23) : "f"(r3), "f"(r2));
    hi = make_uint2(h01, h23); lo = make_uint2(l01, l23);
}
__device__ __forceinline__ void split2(float a, float b, uint32_t& hi, uint32_t& lo) {
    asm("cvt.rn.bf16x2.f32 %0, %1, %2;" : "=r"(hi) : "f"(b), "f"(a));
    float f0 = __uint_as_float(hi << 16);
    float f1 = __uint_as_float(hi & 0xffff0000u);
    float r0 = a - f0, r1 = b - f1;
    asm("cvt.rn.bf16x2.f32 %0, %1, %2;" : "=r"(lo) : "f"(r1), "f"(r0));
}

// ---------------- small kernels -------------------------------------------
__global__ void init_kernel() {
    if (threadIdx.x < NSLOTS) { g_cnt[threadIdx.x] = 0; g_cur[threadIdx.x] = 0; }
}

__global__ void __launch_bounds__(128)
router_kernel(const float* __restrict__ x, const int* __restrict__ tt,
              const float* __restrict__ tw, const float* __restrict__ tb,
              const float* __restrict__ vw, const float* __restrict__ vb,
              float* __restrict__ out_logits)
{
    int t = blockIdx.x;
    int tid = threadIdx.x;
    bool vis = (tt[t] != 0);
    const float* w = vis ? vw : tw;
    const float* b = vis ? vb : tb;

    __shared__ float xs[HID];
    __shared__ float lg[NEXP];
    const float* xr = x + (size_t)t * HID;
    for (int i = tid; i < HID; i += 128) xs[i] = xr[i];
    __syncthreads();

    int e = tid >> 3;
    int l = tid & 7;
    const float* we = w + (size_t)e * HID;
    float s = 0.f;
    for (int k = l; k < HID; k += 8) s += xs[k] * we[k];
    for (int o = 4; o; o >>= 1) s += __shfl_down_sync(0xffffffffu, s, o);
    if (l == 0) lg[e] = s;
    __syncthreads();

    if (tid < NEXP) out_logits[(size_t)t * NEXP + tid] = lg[tid];

    if (tid == 0) {
        float mx = lg[0];
        for (int i = 1; i < NEXP; i++) mx = fmaxf(mx, lg[i]);
        float p[NEXP]; float sum = 0.f;
        for (int i = 0; i < NEXP; i++) { p[i] = expf(lg[i] - mx); sum += p[i]; }
        float inv = 1.f / sum;
        float corr[NEXP];
        for (int i = 0; i < NEXP; i++) { p[i] *= inv; corr[i] = p[i] + b[i]; }

        bool used[NEXP];
        for (int i = 0; i < NEXP; i++) used[i] = false;
        int idxs[TOPK]; float ws[TOPK]; float wsum = 0.f;
        for (int j = 0; j < TOPK; j++) {
            int bi = -1; float bv = -1e30f;
            for (int i = 0; i < NEXP; i++)
                if (!used[i] && corr[i] > bv) { bv = corr[i]; bi = i; }
            used[bi] = true; idxs[j] = bi; ws[j] = p[bi]; wsum += p[bi];
        }
        float invw = 1.f / fmaxf(wsum, 1e-12f);
        int mbase = vis ? 16 : 0;
        for (int j = 0; j < TOPK; j++) {
            g_tope[t*TOPK + j] = mbase + idxs[j];
            g_topw[t*TOPK + j] = ws[j] * invw;
            atomicAdd(&g_cnt[mbase + idxs[j]], 1);
        }
    }
}

// scatter with fused scan (each block computes the 32-slot prefix locally)
__global__ void scatter_kernel() {
    __shared__ int soff[NSLOTS];
    if (threadIdx.x == 0) {
        int acc = 0;
        for (int i = 0; i < NSLOTS; i++) { soff[i] = acc; acc += g_cnt[i]; }
    }
    __syncthreads();
    if (blockIdx.x == 0 && threadIdx.x < NSLOTS) g_off[threadIdx.x] = soff[threadIdx.x];
    int p = blockIdx.x * blockDim.x + threadIdx.x;
    if (p >= NPAIRS) return;
    int slot = g_tope[p];
    int pos = atomicAdd(&g_cur[slot], 1);
    int g = soff[slot] + pos;
    g_slot_tok[g] = p / TOPK;
    g_slot_w[g]   = g_topw[p];
    g_pair_row[p] = g;
}

// ---------------- pre-split fp32 -> bf16 hi/lo planes ----------------------
__global__ void __launch_bounds__(256)
presplit_kernel(const float4* __restrict__ src, int code, int n4)
{
    int i = blockIdx.x * 256 + threadIdx.x;
    if (i >= n4) return;
    __nv_bfloat16 *dh, *dl;
    switch (code) {
        case 0: dh = g_xh;   dl = g_xl;   break;
        case 1: dh = g_tguh; dl = g_tgul; break;
        case 2: dh = g_tdnh; dl = g_tdnl; break;
        case 3: dh = g_vguh; dl = g_vgul; break;
        case 4: dh = g_vdnh; dl = g_vdnl; break;
        case 5: dh = g_sgh;  dl = g_sgl;  break;
        case 6: dh = g_suh;  dl = g_sul;  break;
        default: dh = g_sdh; dl = g_sdl;  break;
    }
    float4 v = src[i];
    uint2 h, l;
    split4(v, h, l);
    ((uint2*)dh)[i] = h;
    ((uint2*)dl)[i] = l;
}

// ---------------- bf16x3 split-precision tensor-core GEMM ------------------
// Operands pre-split in gmem. BM=128, BN=128, BK=32, 2-stage smem pipeline.
// 8 warps: 4 (M) x 2 (N), warp tile 32x64, 3 MMA passes (AhBh+AhBl+AlBh).
#define STG_AH 0
#define STG_AL 10240
#define STG_BH 20480
#define STG_BL 29184
#define STG_SZ 37888
#define GEMM_SMEM (2*STG_SZ)

__global__ void __launch_bounds__(256, 1)
gemm_bf16x3(int acode, int wcode, size_t bstride, int lda, int ldb, int ldc,
            int K, int mode, int slotbase, int scale, int cbuf, int coloff)
{
    extern __shared__ __align__(16) char S[];

    int M, baserow;
    if (mode == 2) { M = T_TOKENS; baserow = 0; }
    else { int s = slotbase + blockIdx.z; M = g_cnt[s]; baserow = g_off[s]; }
    int m0 = blockIdx.x * 128;
    if (m0 >= M) return;
    int n0 = blockIdx.y * 128;

    const __nv_bfloat16 *AHp, *ALp, *BHp, *BLp;
    switch (acode) {
        case 0: AHp = g_xh;    ALp = g_xl;    break;
        case 1: AHp = g_hexph; ALp = g_hexpl; break;
        default: AHp = g_hshh; ALp = g_hshl;  break;
    }
    switch (wcode) {
        case 0: BHp = g_tguh; BLp = g_tgul; break;
        case 1: BHp = g_tdnh; BLp = g_tdnl; break;
        case 2: BHp = g_vguh; BLp = g_vgul; break;
        case 3: BHp = g_vdnh; BLp = g_vdnl; break;
        case 4: BHp = g_sgh;  BLp = g_sgl;  break;
        case 5: BHp = g_suh;  BLp = g_sul;  break;
        default: BHp = g_sdh; BLp = g_sdl;  break;
    }
    size_t bs = (size_t)blockIdx.z * bstride;
    BHp += bs; BLp += bs;

    float* Cb = ((cbuf == 0) ? g_cgu : (cbuf == 1) ? g_csh :
                 (cbuf == 2) ? g_oexp : g_osh) + coloff;

    int tid = threadIdx.x, lane = tid & 31, wid = tid >> 5;
    int wm = wid & 3, wn = wid >> 2;

    // loader roles: threads 0-127 handle hi planes, 128-255 lo planes
    int half = tid >> 7;
    int lr = tid & 127;

    // A: one row (32 cols of chunk) per thread
    int rclamp = min(m0 + lr, M - 1);
    size_t arow;
    if (mode == 0)      arow = (size_t)g_slot_tok[baserow + rclamp] * lda;
    else if (mode == 1) arow = (size_t)(baserow + rclamp) * lda;
    else                arow = (size_t)rclamp * lda;
    const __nv_bfloat16* Ap = (half ? ALp : AHp) + arow;
    uint32_t aSts = (half ? STG_AL : STG_AH) + (uint32_t)lr * 80u;

    // B: bk row, 32-col segment per thread
    int bk = lr >> 2, bn = (lr & 3) * 32;
    const __nv_bfloat16* Bp = (half ? BLp : BHp) + n0 + bn;
    uint32_t bSts = (half ? STG_BL : STG_BH) + (uint32_t)bk * 272u + (uint32_t)bn * 2u;

    float acc[2][8][4];
    #pragma unroll
    for (int i = 0; i < 2; i++)
        #pragma unroll
        for (int j = 0; j < 8; j++)
            #pragma unroll
            for (int q = 0; q < 4; q++) acc[i][j][q] = 0.f;

    uint4 va[4], vb[4];
    uint32_t sbase = smem_u32(S);
    const int NCH = K / 32;

    // --- prologue: chunk0 -> regs -> stage0; chunk1 -> regs ---
    {
        const uint4* ap = (const uint4*)(Ap + 0);
        const uint4* bp = (const uint4*)(Bp + (size_t)bk * ldb);
        #pragma unroll
        for (int q = 0; q < 4; q++) { va[q] = ap[q]; vb[q] = bp[q]; }
        #pragma unroll
        for (int q = 0; q < 4; q++) {
            *(uint4*)(S + aSts + q*16) = va[q];
            *(uint4*)(S + bSts + q*16) = vb[q];
        }
        const uint4* ap1 = (const uint4*)(Ap + 32);
        const uint4* bp1 = (const uint4*)(Bp + (size_t)(32 + bk) * ldb);
        #pragma unroll
        for (int q = 0; q < 4; q++) { va[q] = ap1[q]; vb[q] = bp1[q]; }
    }
    __syncthreads();

    for (int c = 0; c < NCH; c++) {
        int cur = c & 1;
        // store chunk c+1 (in regs) into the other stage
        if (c + 1 < NCH) {
            char* st = S + (cur ^ 1) * STG_SZ;
            #pragma unroll
            for (int q = 0; q < 4; q++) {
                *(uint4*)(st + aSts + q*16) = va[q];
                *(uint4*)(st + bSts + q*16) = vb[q];
            }
        }
        // prefetch chunk c+2
        if (c + 2 < NCH) {
            int k0 = (c + 2) * 32;
            const uint4* ap = (const uint4*)(Ap + k0);
            const uint4* bp = (const uint4*)(Bp + (size_t)(k0 + bk) * ldb);
            #pragma unroll
            for (int q = 0; q < 4; q++) { va[q] = ap[q]; vb[q] = bp[q]; }
        }
        // compute on stage cur
        uint32_t sb = sbase + (uint32_t)cur * STG_SZ;
        #pragma unroll
        for (int ks = 0; ks < 2; ks++) {
            uint32_t ah[2][4], al[2][4], bh[8][2], bl[8][2];
            #pragma unroll
            for (int mi = 0; mi < 2; mi++) {
                uint32_t ra = (uint32_t)(wm*32 + mi*16 + (lane & 15)) * 80u
                            + (uint32_t)(ks*32) + (uint32_t)((lane >> 4) * 16);
                LDSM4(ah[mi][0], ah[mi][1], ah[mi][2], ah[mi][3], sb + STG_AH + ra);
                LDSM4(al[mi][0], al[mi][1], al[mi][2], al[mi][3], sb + STG_AL + ra);
            }
            #pragma unroll
            for (int p = 0; p < 4; p++) {
                uint32_t rb = (uint32_t)(ks*16 + (lane & 15)) * 272u
                            + (uint32_t)((wn*64 + p*16 + ((lane >> 4) * 8)) * 2);
                LDSM4T(bh[2*p][0], bh[2*p][1], bh[2*p+1][0], bh[2*p+1][1], sb + STG_BH + rb);
                LDSM4T(bl[2*p][0], bl[2*p][1], bl[2*p+1][0], bl[2*p+1][1], sb + STG_BL + rb);
            }
            #pragma unroll
            for (int mi = 0; mi < 2; mi++)
                #pragma unroll
                for (int nj = 0; nj < 8; nj++) {
                    MMA(acc[mi][nj], ah[mi][0], ah[mi][1], ah[mi][2], ah[mi][3],
                        bh[nj][0], bh[nj][1]);
                    MMA(acc[mi][nj], ah[mi][0], ah[mi][1], ah[mi][2], ah[mi][3],
                        bl[nj][0], bl[nj][1]);
                    MMA(acc[mi][nj], al[mi][0], al[mi][1], al[mi][2], al[mi][3],
                        bh[nj][0], bh[nj][1]);
                }
        }
        __syncthreads();
    }

    // epilogue
    #pragma unroll
    for (int mi = 0; mi < 2; mi++) {
        int row0 = m0 + wm*32 + mi*16 + (lane >> 2);
        int row1 = row0 + 8;
        float w0 = 1.f, w1 = 1.f;
        if (scale) {
            if (row0 < M) w0 = g_slot_w[baserow + row0];
            if (row1 < M) w1 = g_slot_w[baserow + row1];
        }
        #pragma unroll
        for (int nj = 0; nj < 8; nj++) {
            int col = n0 + wn*64 + nj*8 + (lane & 3)*2;
            if (row0 < M) {
                float2 v = make_float2(acc[mi][nj][0]*w0, acc[mi][nj][1]*w0);
                *(float2*)(Cb + (size_t)(baserow + row0)*ldc + col) = v;
            }
            if (row1 < M) {
                float2 v = make_float2(acc[mi][nj][2]*w1, acc[mi][nj][3]*w1);
                *(float2*)(Cb + (size_t)(baserow + row1)*ldc + col) = v;
            }
        }
    }
}

// ---------------- elementwise SiLU * up -> pre-split hi/lo -----------------
__global__ void __launch_bounds__(256)
silu_experts()
{
    int row = blockIdx.y;
    int i2 = blockIdx.x * 256 + threadIdx.x;   // pair index
    int boundary = g_off[16];                  // first vis row
    int I = (row < boundary) ? TI : VI;
    int i = i2 * 2;
    if (i >= I) return;
    const float* crow = g_cgu + (size_t)row * (2*TI);
    float ga = crow[i],     ua = crow[I + i];
    float gb = crow[i + 1], ub = crow[I + i + 1];
    float ha = ga / (1.f + __expf(-ga)) * ua;
    float hb = gb / (1.f + __expf(-gb)) * ub;
    uint32_t hi, lo;
    split2(ha, hb, hi, lo);
    size_t o = (size_t)row * TI + i;
    *(uint32_t*)(g_hexph + o) = hi;
    *(uint32_t*)(g_hexpl + o) = lo;
}

__global__ void __launch_bounds__(256)
silu_shared()
{
    int row = blockIdx.y;
    int i = (blockIdx.x * 256 + threadIdx.x) * 2;
    const float* crow = g_csh + (size_t)row * (2*SI);
    float ga = crow[i],     ua = crow[SI + i];
    float gb = crow[i + 1], ub = crow[SI + i + 1];
    float ha = ga / (1.f + __expf(-ga)) * ua;
    float hb = gb / (1.f + __expf(-gb)) * ub;
    uint32_t hi, lo;
    split2(ha, hb, hi, lo);
    size_t o = (size_t)row * SI + i;
    *(uint32_t*)(g_hshh + o) = hi;
    *(uint32_t*)(g_hshl + o) = lo;
}

// ---------------- finalize: gather 6 expert rows + shared ------------------
__global__ void __launch_bounds__(256)
finalize_kernel(float* __restrict__ out)
{
    int t = blockIdx.y;
    int h = blockIdx.x * 256 + threadIdx.x;
    float s = g_osh[(size_t)t * HID + h];
    #pragma unroll
    for (int j = 0; j < TOPK; j++) {
        int g = g_pair_row[t*TOPK + j];
        s += g_oexp[(size_t)g * HID + h];
    }
    out[(size_t)t * HID + h] = s;
}

// ---------------- launch ----------------------------------------------------
static inline void presplit(const void* src, int code, size_t n) {
    int n4 = (int)(n / 4);
    presplit_kernel<<<(n4 + 255)/256, 256>>>((const float4*)src, code, n4);
}

extern "C" void kernel_launch(void* const* d_in, const int* in_sizes, int n_in,
                              void* d_out, int out_size)
{
    (void)in_sizes; (void)n_in; (void)out_size;
    const float* x   = (const float*)d_in[0];
    const int*   tt  = (const int*)  d_in[1];
    const float* trw = (const float*)d_in[2];
    const float* trb = (const float*)d_in[3];
    const float* tgu = (const float*)d_in[4];
    const float* tdn = (const float*)d_in[5];
    const float* vrw = (const float*)d_in[6];
    const float* vrb = (const float*)d_in[7];
    const float* vgu = (const float*)d_in[8];
    const float* vdn = (const float*)d_in[9];
    const float* sg  = (const float*)d_in[10];
    const float* su  = (const float*)d_in[11];
    const float* sd  = (const float*)d_in[12];
    float* out        = (float*)d_out;
    float* out_logits = out + (size_t)T_TOKENS * HID;

    cudaFuncSetAttribute(gemm_bf16x3, cudaFuncAttributeMaxDynamicSharedMemorySize, GEMM_SMEM);

    init_kernel<<<1, 32>>>();                                               // 1
    router_kernel<<<T_TOKENS, 128>>>(x, tt, trw, trb, vrw, vrb, out_logits);// 2
    scatter_kernel<<<NPAIRS/256, 256>>>();                                  // 3

    presplit(x,   0, (size_t)T_TOKENS*HID);                                 // 4
    presplit(tgu, 1, (size_t)NEXP*HID*2*TI);                                // 5
    // 6: main text gate/up GEMM (ncu -s 5 -c 1 lands here)
    gemm_bf16x3<<<dim3(32, (2*TI)/128, 16), 256, GEMM_SMEM>>>(
        0, 0, (size_t)HID*2*TI, HID, 2*TI, 2*TI, HID, 0, 0,  0, 0, 0);

    presplit(vgu, 3, (size_t)NEXP*HID*2*VI);
    gemm_bf16x3<<<dim3(32, (2*VI)/128, 16), 256, GEMM_SMEM>>>(
        0, 2, (size_t)HID*2*VI, HID, 2*VI, 2*TI, HID, 0, 16, 0, 0, 0);

    presplit(sg, 5, (size_t)HID*SI);
    presplit(su, 6, (size_t)HID*SI);
    gemm_bf16x3<<<dim3(32, SI/128, 1), 256, GEMM_SMEM>>>(
        0, 4, 0, HID, SI, 2*SI, HID, 2, 0, 0, 1, 0);
    gemm_bf16x3<<<dim3(32, SI/128, 1), 256, GEMM_SMEM>>>(
        0, 5, 0, HID, SI, 2*SI, HID, 2, 0, 0, 1, SI);

    silu_experts<<<dim3(TI/512, NPAIRS), 256>>>();
    silu_shared<<<dim3(SI/512, T_TOKENS), 256>>>();

    presplit(tdn, 2, (size_t)NEXP*TI*HID);
    gemm_bf16x3<<<dim3(32, HID/128, 16), 256, GEMM_SMEM>>>(
        1, 1, (size_t)TI*HID, TI, HID, HID, TI, 1, 0,  1, 2, 0);
    presplit(vdn, 4, (size_t)NEXP*VI*HID);
    gemm_bf16x3<<<dim3(32, HID/128, 16), 256, GEMM_SMEM>>>(
        1, 3, (size_t)VI*HID, TI, HID, HID, VI, 1, 16, 1, 2, 0);
    presplit(sd, 7, (size_t)SI*HID);
    gemm_bf16x3<<<dim3(32, HID/128, 1), 256, GEMM_SMEM>>>(
        2, 6, 0, SI, HID, HID, SI, 2, 0, 0, 3, 0);

    finalize_kernel<<<dim3(HID/256, T_TOKENS), 256>>>(out);
}

// round 14
// speedup vs baseline: 2.2847x; 1.2142x over previous
#include <cuda_runtime.h>
#include <cuda_fp16.h>
#include <math.h>
#include <stdint.h>

#define T_TOKENS 4096
#define HID 2560
#define NEXP 16
#define TOPK 6
#define TI 1536
#define VI 512
#define SI 3072
#define NPAIRS (T_TOKENS*TOPK)   /* 24576 */
#define NSLOTS 32

// ---------------- scratch (device globals; no runtime allocation) ----------
__device__ float g_cgu[(size_t)NPAIRS * (2*TI)];   // gate_up GEMM out (experts)
__device__ float g_csh[(size_t)T_TOKENS * (2*SI)]; // gate/up GEMM out (shared)
__device__ float g_oexp[(size_t)NPAIRS * HID];     // weighted down out per pair
__device__ float g_osh[(size_t)T_TOKENS * HID];    // shared down out

// fp16 hi/lo planes for activations only (weights converted inline in GEMM)
__device__ __half g_xh[(size_t)T_TOKENS*HID],    g_xl[(size_t)T_TOKENS*HID];
__device__ __half g_hexph[(size_t)NPAIRS*TI],    g_hexpl[(size_t)NPAIRS*TI];
__device__ __half g_hshh[(size_t)T_TOKENS*SI],   g_hshl[(size_t)T_TOKENS*SI];

__device__ int   g_slot_tok[NPAIRS];
__device__ float g_slot_w[NPAIRS];
__device__ int   g_pair_row[NPAIRS];
__device__ int   g_cnt[NSLOTS];
__device__ int   g_off[NSLOTS];
__device__ int   g_cur[NSLOTS];
__device__ int   g_tope[NPAIRS];
__device__ float g_topw[NPAIRS];

// ---------------- helpers ---------------------------------------------------
__device__ __forceinline__ uint32_t smem_u32(const void* p) {
    return (uint32_t)__cvta_generic_to_shared(p);
}

#define LDSM4(R0,R1,R2,R3,A) \
    asm volatile("ldmatrix.sync.aligned.m8n8.x4.shared.b16 {%0,%1,%2,%3}, [%4];" \
        : "=r"(R0), "=r"(R1), "=r"(R2), "=r"(R3) : "r"(A))
#define LDSM4T(R0,R1,R2,R3,A) \
    asm volatile("ldmatrix.sync.aligned.m8n8.x4.trans.shared.b16 {%0,%1,%2,%3}, [%4];" \
        : "=r"(R0), "=r"(R1), "=r"(R2), "=r"(R3) : "r"(A))
#define MMAF16(D,A0,A1,A2,A3,B0,B1) \
    asm volatile("mma.sync.aligned.m16n8k16.row.col.f32.f16.f16.f32 " \
        "{%0,%1,%2,%3}, {%4,%5,%6,%7}, {%8,%9}, {%0,%1,%2,%3};" \
        : "+f"((D)[0]), "+f"((D)[1]), "+f"((D)[2]), "+f"((D)[3]) \
        : "r"(A0), "r"(A1), "r"(A2), "r"(A3), "r"(B0), "r"(B1))

// pack two fp32 -> fp16x2 (a -> low half, b -> high half)
__device__ __forceinline__ uint32_t pkh(float a, float b) {
    uint32_t r;
    asm("cvt.rn.f16x2.f32 %0, %1, %2;" : "=r"(r) : "f"(b), "f"(a));
    return r;
}
// split two fp32 into fp16 hi pair + fp16 residual pair
__device__ __forceinline__ void split2h(float a, float b, uint32_t& hi, uint32_t& lo) {
    hi = pkh(a, b);
    __half2 h = *reinterpret_cast<__half2*>(&hi);
    float2 f = __half22float2(h);
    lo = pkh(a - f.x, b - f.y);
}

// ---------------- small kernels -------------------------------------------
__global__ void init_kernel() {
    if (threadIdx.x < NSLOTS) { g_cnt[threadIdx.x] = 0; g_cur[threadIdx.x] = 0; }
}

// pre-split x: fp32 -> fp16 hi/lo planes
__global__ void __launch_bounds__(256)
presplit_x(const float4* __restrict__ src, int n4)
{
    int i = blockIdx.x * 256 + threadIdx.x;
    if (i >= n4) return;
    float4 v = src[i];
    uint32_t h0, l0, h1, l1;
    split2h(v.x, v.y, h0, l0);
    split2h(v.z, v.w, h1, l1);
    ((uint2*)g_xh)[i] = make_uint2(h0, h1);
    ((uint2*)g_xl)[i] = make_uint2(l0, l1);
}

__global__ void __launch_bounds__(128)
router_kernel(const float* __restrict__ x, const int* __restrict__ tt,
              const float* __restrict__ tw, const float* __restrict__ tb,
              const float* __restrict__ vw, const float* __restrict__ vb,
              float* __restrict__ out_logits)
{
    int t = blockIdx.x;
    int tid = threadIdx.x;
    bool vis = (tt[t] != 0);
    const float* w = vis ? vw : tw;
    const float* b = vis ? vb : tb;

    __shared__ float xs[HID];
    __shared__ float lg[NEXP];
    const float* xr = x + (size_t)t * HID;
    for (int i = tid; i < HID; i += 128) xs[i] = xr[i];
    __syncthreads();

    int e = tid >> 3;
    int l = tid & 7;
    const float* we = w + (size_t)e * HID;
    float s = 0.f;
    for (int k = l; k < HID; k += 8) s += xs[k] * we[k];
    for (int o = 4; o; o >>= 1) s += __shfl_down_sync(0xffffffffu, s, o);
    if (l == 0) lg[e] = s;
    __syncthreads();

    if (tid < NEXP) out_logits[(size_t)t * NEXP + tid] = lg[tid];

    if (tid == 0) {
        float mx = lg[0];
        for (int i = 1; i < NEXP; i++) mx = fmaxf(mx, lg[i]);
        float p[NEXP]; float sum = 0.f;
        for (int i = 0; i < NEXP; i++) { p[i] = expf(lg[i] - mx); sum += p[i]; }
        float inv = 1.f / sum;
        float corr[NEXP];
        for (int i = 0; i < NEXP; i++) { p[i] *= inv; corr[i] = p[i] + b[i]; }

        bool used[NEXP];
        for (int i = 0; i < NEXP; i++) used[i] = false;
        int idxs[TOPK]; float ws[TOPK]; float wsum = 0.f;
        for (int j = 0; j < TOPK; j++) {
            int bi = -1; float bv = -1e30f;
            for (int i = 0; i < NEXP; i++)
                if (!used[i] && corr[i] > bv) { bv = corr[i]; bi = i; }
            used[bi] = true; idxs[j] = bi; ws[j] = p[bi]; wsum += p[bi];
        }
        float invw = 1.f / fmaxf(wsum, 1e-12f);
        int mbase = vis ? 16 : 0;
        for (int j = 0; j < TOPK; j++) {
            g_tope[t*TOPK + j] = mbase + idxs[j];
            g_topw[t*TOPK + j] = ws[j] * invw;
            atomicAdd(&g_cnt[mbase + idxs[j]], 1);
        }
    }
}

// scatter with fused scan (each block computes the 32-slot prefix locally)
__global__ void scatter_kernel() {
    __shared__ int soff[NSLOTS];
    if (threadIdx.x == 0) {
        int acc = 0;
        for (int i = 0; i < NSLOTS; i++) { soff[i] = acc; acc += g_cnt[i]; }
    }
    __syncthreads();
    if (blockIdx.x == 0 && threadIdx.x < NSLOTS) g_off[threadIdx.x] = soff[threadIdx.x];
    int p = blockIdx.x * blockDim.x + threadIdx.x;
    if (p >= NPAIRS) return;
    int slot = g_tope[p];
    int pos = atomicAdd(&g_cur[slot], 1);
    int g = soff[slot] + pos;
    g_slot_tok[g] = p / TOPK;
    g_slot_w[g]   = g_topw[p];
    g_pair_row[p] = g;
}

// ---------------- fp16x2 split-precision tensor-core GEMM ------------------
// C = (Ah+Al) @ fp16(B): 2 MMA passes. A pre-split fp16 planes in gmem;
// B fp32 weights converted to fp16 inline in the loader.
// BM=128, BN=128, BK=32, 2-stage smem pipeline, 8 warps 4(M)x2(N).
#define STG_AH 0
#define STG_AL 10240
#define STG_B  20480
#define STG_SZ 29184
#define GEMM_SMEM (2*STG_SZ)

__global__ void __launch_bounds__(256, 1)
gemm_f16x2(int acode, const float* __restrict__ Bw,
           size_t bstride, int lda, int ldb, int ldc,
           int K, int mode, int slotbase, int scale, int cbuf, int coloff)
{
    extern __shared__ __align__(16) char S[];

    int M, baserow;
    if (mode == 2) { M = T_TOKENS; baserow = 0; }
    else { int s = slotbase + blockIdx.z; M = g_cnt[s]; baserow = g_off[s]; }
    int m0 = blockIdx.x * 128;
    if (m0 >= M) return;
    int n0 = blockIdx.y * 128;

    const __half *AHp, *ALp;
    switch (acode) {
        case 0: AHp = g_xh;    ALp = g_xl;    break;
        case 1: AHp = g_hexph; ALp = g_hexpl; break;
        default: AHp = g_hshh; ALp = g_hshl;  break;
    }
    const float* Bbase = Bw + (size_t)blockIdx.z * bstride;

    float* Cb = ((cbuf == 0) ? g_cgu : (cbuf == 1) ? g_csh :
                 (cbuf == 2) ? g_oexp : g_osh) + coloff;

    int tid = threadIdx.x, lane = tid & 31, wid = tid >> 5;
    int wm = wid & 3, wn = wid >> 2;

    // A loader: threads 0-127 hi plane, 128-255 lo plane; 1 row x 32 halfs each
    int half_ = tid >> 7;
    int lr = tid & 127;
    int rclamp = min(m0 + lr, M - 1);
    size_t arow;
    if (mode == 0)      arow = (size_t)g_slot_tok[baserow + rclamp] * lda;
    else if (mode == 1) arow = (size_t)(baserow + rclamp) * lda;
    else                arow = (size_t)rclamp * lda;
    const __half* Ap = (half_ ? ALp : AHp) + arow;
    uint32_t aSts = (half_ ? STG_AL : STG_AH) + (uint32_t)lr * 80u;

    // B loader: all 256 threads; row bk (0..31), 16 fp32 cols -> 16 fp16
    int bk = tid >> 3, bn = (tid & 7) * 16;
    const float* Bp = Bbase + n0 + bn;
    uint32_t bSts = STG_B + (uint32_t)bk * 272u + (uint32_t)bn * 2u;

    float acc[2][8][4];
    #pragma unroll
    for (int i = 0; i < 2; i++)
        #pragma unroll
        for (int j = 0; j < 8; j++)
            #pragma unroll
            for (int q = 0; q < 4; q++) acc[i][j][q] = 0.f;

    uint4 va[4];
    float4 fb[4];
    uint32_t sbase = smem_u32(S);
    const int NCH = K / 32;

    // --- prologue: chunk0 -> stage0; chunk1 -> regs ---
    {
        const uint4* ap = (const uint4*)(Ap + 0);
        const float4* bp = (const float4*)(Bp + (size_t)bk * ldb);
        #pragma unroll
        for (int q = 0; q < 4; q++) { va[q] = ap[q]; fb[q] = bp[q]; }
        #pragma unroll
        for (int q = 0; q < 4; q++) *(uint4*)(S + aSts + q*16) = va[q];
        *(uint4*)(S + bSts) = make_uint4(
            pkh(fb[0].x, fb[0].y), pkh(fb[0].z, fb[0].w),
            pkh(fb[1].x, fb[1].y), pkh(fb[1].z, fb[1].w));
        *(uint4*)(S + bSts + 16) = make_uint4(
            pkh(fb[2].x, fb[2].y), pkh(fb[2].z, fb[2].w),
            pkh(fb[3].x, fb[3].y), pkh(fb[3].z, fb[3].w));
        const uint4* ap1 = (const uint4*)(Ap + 32);
        const float4* bp1 = (const float4*)(Bp + (size_t)(32 + bk) * ldb);
        #pragma unroll
        for (int q = 0; q < 4; q++) { va[q] = ap1[q]; fb[q] = bp1[q]; }
    }
    __syncthreads();

    for (int c = 0; c < NCH; c++) {
        int cur = c & 1;
        // store chunk c+1 (in regs) into the other stage
        if (c + 1 < NCH) {
            char* st = S + (cur ^ 1) * STG_SZ;
            #pragma unroll
            for (int q = 0; q < 4; q++) *(uint4*)(st + aSts + q*16) = va[q];
            *(uint4*)(st + bSts) = make_uint4(
                pkh(fb[0].x, fb[0].y), pkh(fb[0].z, fb[0].w),
                pkh(fb[1].x, fb[1].y), pkh(fb[1].z, fb[1].w));
            *(uint4*)(st + bSts + 16) = make_uint4(
                pkh(fb[2].x, fb[2].y), pkh(fb[2].z, fb[2].w),
                pkh(fb[3].x, fb[3].y), pkh(fb[3].z, fb[3].w));
        }
        // prefetch chunk c+2
        if (c + 2 < NCH) {
            int k0 = (c + 2) * 32;
            const uint4* ap = (const uint4*)(Ap + k0);
            const float4* bp = (const float4*)(Bp + (size_t)(k0 + bk) * ldb);
            #pragma unroll
            for (int q = 0; q < 4; q++) { va[q] = ap[q]; fb[q] = bp[q]; }
        }
        // compute on stage cur
        uint32_t sb = sbase + (uint32_t)cur * STG_SZ;
        #pragma unroll
        for (int ks = 0; ks < 2; ks++) {
            uint32_t ah[2][4], al[2][4], b[8][2];
            #pragma unroll
            for (int mi = 0; mi < 2; mi++) {
                uint32_t ra = (uint32_t)(wm*32 + mi*16 + (lane & 15)) * 80u
                            + (uint32_t)(ks*32) + (uint32_t)((lane >> 4) * 16);
                LDSM4(ah[mi][0], ah[mi][1], ah[mi][2], ah[mi][3], sb + STG_AH + ra);
                LDSM4(al[mi][0], al[mi][1], al[mi][2], al[mi][3], sb + STG_AL + ra);
            }
            #pragma unroll
            for (int p = 0; p < 4; p++) {
                uint32_t rb = (uint32_t)(ks*16 + (lane & 15)) * 272u
                            + (uint32_t)((wn*64 + p*16 + ((lane >> 4) * 8)) * 2);
                LDSM4T(b[2*p][0], b[2*p][1], b[2*p+1][0], b[2*p+1][1], sb + STG_B + rb);
            }
            #pragma unroll
            for (int mi = 0; mi < 2; mi++)
                #pragma unroll
                for (int nj = 0; nj < 8; nj++) {
                    MMAF16(acc[mi][nj], ah[mi][0], ah[mi][1], ah[mi][2], ah[mi][3],
                           b[nj][0], b[nj][1]);
                    MMAF16(acc[mi][nj], al[mi][0], al[mi][1], al[mi][2], al[mi][3],
                           b[nj][0], b[nj][1]);
                }
        }
        __syncthreads();
    }

    // epilogue
    #pragma unroll
    for (int mi = 0; mi < 2; mi++) {
        int row0 = m0 + wm*32 + mi*16 + (lane >> 2);
        int row1 = row0 + 8;
        float w0 = 1.f, w1 = 1.f;
        if (scale) {
            if (row0 < M) w0 = g_slot_w[baserow + row0];
            if (row1 < M) w1 = g_slot_w[baserow + row1];
        }
        #pragma unroll
        for (int nj = 0; nj < 8; nj++) {
            int col = n0 + wn*64 + nj*8 + (lane & 3)*2;
            if (row0 < M) {
                float2 v = make_float2(acc[mi][nj][0]*w0, acc[mi][nj][1]*w0);
                *(float2*)(Cb + (size_t)(baserow + row0)*ldc + col) = v;
            }
            if (row1 < M) {
                float2 v = make_float2(acc[mi][nj][2]*w1, acc[mi][nj][3]*w1);
                *(float2*)(Cb + (size_t)(baserow + row1)*ldc + col) = v;
            }
        }
    }
}

// ---------------- elementwise SiLU * up -> fp16 hi/lo planes ---------------
__global__ void __launch_bounds__(256)
silu_experts()
{
    int row = blockIdx.y;
    int i = (blockIdx.x * 256 + threadIdx.x) * 2;
    int boundary = g_off[16];               // first vis row
    int I = (row < boundary) ? TI : VI;
    if (i >= I) return;
    const float* crow = g_cgu + (size_t)row * (2*TI);
    float ga = crow[i],     ua = crow[I + i];
    float gb = crow[i + 1], ub = crow[I + i + 1];
    float ha = ga / (1.f + __expf(-ga)) * ua;
    float hb = gb / (1.f + __expf(-gb)) * ub;
    uint32_t hi, lo;
    split2h(ha, hb, hi, lo);
    size_t o = (size_t)row * TI + i;
    *(uint32_t*)(g_hexph + o) = hi;
    *(uint32_t*)(g_hexpl + o) = lo;
}

__global__ void __launch_bounds__(256)
silu_shared()
{
    int row = blockIdx.y;
    int i = (blockIdx.x * 256 + threadIdx.x) * 2;
    const float* crow = g_csh + (size_t)row * (2*SI);
    float ga = crow[i],     ua = crow[SI + i];
    float gb = crow[i + 1], ub = crow[SI + i + 1];
    float ha = ga / (1.f + __expf(-ga)) * ua;
    float hb = gb / (1.f + __expf(-gb)) * ub;
    uint32_t hi, lo;
    split2h(ha, hb, hi, lo);
    size_t o = (size_t)row * SI + i;
    *(uint32_t*)(g_hshh + o) = hi;
    *(uint32_t*)(g_hshl + o) = lo;
}

// ---------------- finalize: gather 6 expert rows + shared ------------------
__global__ void __launch_bounds__(256)
finalize_kernel(float* __restrict__ out)
{
    int t = blockIdx.y;
    int h = blockIdx.x * 256 + threadIdx.x;
    float s = g_osh[(size_t)t * HID + h];
    #pragma unroll
    for (int j = 0; j < TOPK; j++) {
        int g = g_pair_row[t*TOPK + j];
        s += g_oexp[(size_t)g * HID + h];
    }
    out[(size_t)t * HID + h] = s;
}

// ---------------- launch ----------------------------------------------------
extern "C" void kernel_launch(void* const* d_in, const int* in_sizes, int n_in,
                              void* d_out, int out_size)
{
    (void)in_sizes; (void)n_in; (void)out_size;
    const float* x   = (const float*)d_in[0];
    const int*   tt  = (const int*)  d_in[1];
    const float* trw = (const float*)d_in[2];
    const float* trb = (const float*)d_in[3];
    const float* tgu = (const float*)d_in[4];
    const float* tdn = (const float*)d_in[5];
    const float* vrw = (const float*)d_in[6];
    const float* vrb = (const float*)d_in[7];
    const float* vgu = (const float*)d_in[8];
    const float* vdn = (const float*)d_in[9];
    const float* sg  = (const float*)d_in[10];
    const float* su  = (const float*)d_in[11];
    const float* sd  = (const float*)d_in[12];
    float* out        = (float*)d_out;
    float* out_logits = out + (size_t)T_TOKENS * HID;

    cudaFuncSetAttribute(gemm_f16x2, cudaFuncAttributeMaxDynamicSharedMemorySize, GEMM_SMEM);

    // 1: x pre-split (only data the dense shared GEMMs need)
    presplit_x<<<(T_TOKENS*HID/4 + 255)/256, 256>>>((const float4*)x, T_TOKENS*HID/4);
    // 2: shared-expert gate GEMM (dense; independent of router)
    gemm_f16x2<<<dim3(32, SI/128, 1), 256, GEMM_SMEM>>>(
        0, sg, 0, HID, SI, 2*SI, HID, 2, 0, 0, 1, 0);
    // 3
    init_kernel<<<1, 32>>>();
    // 4: shared-expert up GEMM — ncu profiled slot
    gemm_f16x2<<<dim3(32, SI/128, 1), 256, GEMM_SMEM>>>(
        0, su, 0, HID, SI, 2*SI, HID, 2, 0, 0, 1, SI);
    // 5
    router_kernel<<<T_TOKENS, 128>>>(x, tt, trw, trb, vrw, vrb, out_logits);
    // 6
    scatter_kernel<<<NPAIRS/256, 256>>>();

    // expert gate/up GEMMs
    gemm_f16x2<<<dim3(32, (2*TI)/128, 16), 256, GEMM_SMEM>>>(
        0, tgu, (size_t)HID*2*TI, HID, 2*TI, 2*TI, HID, 0, 0,  0, 0, 0);
    gemm_f16x2<<<dim3(32, (2*VI)/128, 16), 256, GEMM_SMEM>>>(
        0, vgu, (size_t)HID*2*VI, HID, 2*VI, 2*TI, HID, 0, 16, 0, 0, 0);

    silu_shared<<<dim3(SI/512, T_TOKENS), 256>>>();
    silu_experts<<<dim3(TI/512, NPAIRS), 256>>>();

    // down GEMMs
    gemm_f16x2<<<dim3(32, HID/128, 16), 256, GEMM_SMEM>>>(
        1, tdn, (size_t)TI*HID, TI, HID, HID, TI, 1, 0,  1, 2, 0);
    gemm_f16x2<<<dim3(32, HID/128, 16), 256, GEMM_SMEM>>>(
        1, vdn, (size_t)VI*HID, TI, HID, HID, VI, 1, 16, 1, 2, 0);
    gemm_f16x2<<<dim3(32, HID/128, 1), 256, GEMM_SMEM>>>(
        2, sd, 0, SI, HID, HID, SI, 2, 0, 0, 3, 0);

    finalize_kernel<<<dim3(HID/256, T_TOKENS), 256>>>(out);
}

// round 16
// speedup vs baseline: 3.2999x; 1.4443x over previous
#include <cuda_runtime.h>
#include <cuda_fp16.h>
#include <math.h>
#include <stdint.h>

#define T_TOKENS 4096
#define HID 2560
#define NEXP 16
#define TOPK 6
#define TI 1536
#define VI 512
#define SI 3072
#define NPAIRS (T_TOKENS*TOPK)   /* 24576 */
#define NSLOTS 32

// ---------------- scratch (device globals; no runtime allocation) ----------
__device__ float g_cgu[(size_t)NPAIRS * (2*TI)];   // gate_up GEMM out (experts)
__device__ float g_csh[(size_t)T_TOKENS * (2*SI)]; // gate/up GEMM out (shared)
__device__ float g_oexp[(size_t)NPAIRS * HID];     // weighted down out per pair
__device__ float g_osh[(size_t)T_TOKENS * HID];    // shared down out

// fp16 activation hi/lo planes
__device__ __half g_xh[(size_t)T_TOKENS*HID],    g_xl[(size_t)T_TOKENS*HID];
__device__ __half g_hexph[(size_t)NPAIRS*TI],    g_hexpl[(size_t)NPAIRS*TI];
__device__ __half g_hshh[(size_t)T_TOKENS*SI],   g_hshl[(size_t)T_TOKENS*SI];

// fp16 weight planes (converted once per launch)
__device__ __half g_tguh[(size_t)NEXP*HID*2*TI];
__device__ __half g_tdnh[(size_t)NEXP*TI*HID];
__device__ __half g_vguh[(size_t)NEXP*HID*2*VI];
__device__ __half g_vdnh[(size_t)NEXP*VI*HID];
__device__ __half g_sgh[(size_t)HID*SI];
__device__ __half g_suh[(size_t)HID*SI];
__device__ __half g_sdh[(size_t)SI*HID];

__device__ int   g_slot_tok[NPAIRS];
__device__ float g_slot_w[NPAIRS];
__device__ int   g_pair_row[NPAIRS];
__device__ int   g_cnt[NSLOTS];
__device__ int   g_off[NSLOTS];
__device__ int   g_cur[NSLOTS];
__device__ int   g_tope[NPAIRS];
__device__ float g_topw[NPAIRS];

// ---------------- helpers ---------------------------------------------------
__device__ __forceinline__ uint32_t smem_u32(const void* p) {
    return (uint32_t)__cvta_generic_to_shared(p);
}
__device__ __forceinline__ void cp_async16(uint32_t saddr, const void* gaddr) {
    asm volatile("cp.async.cg.shared.global [%0], [%1], 16;"
                 :: "r"(saddr), "l"(gaddr) : "memory");
}
#define CP_COMMIT() asm volatile("cp.async.commit_group;" ::: "memory")
#define CP_WAIT(n)  asm volatile("cp.async.wait_group %0;" :: "n"(n) : "memory")

#define LDSM4(R0,R1,R2,R3,A) \
    asm volatile("ldmatrix.sync.aligned.m8n8.x4.shared.b16 {%0,%1,%2,%3}, [%4];" \
        : "=r"(R0), "=r"(R1), "=r"(R2), "=r"(R3) : "r"(A))
#define LDSM4T(R0,R1,R2,R3,A) \
    asm volatile("ldmatrix.sync.aligned.m8n8.x4.trans.shared.b16 {%0,%1,%2,%3}, [%4];" \
        : "=r"(R0), "=r"(R1), "=r"(R2), "=r"(R3) : "r"(A))
#define MMAF16(D,A0,A1,A2,A3,B0,B1) \
    asm volatile("mma.sync.aligned.m16n8k16.row.col.f32.f16.f16.f32 " \
        "{%0,%1,%2,%3}, {%4,%5,%6,%7}, {%8,%9}, {%0,%1,%2,%3};" \
        : "+f"((D)[0]), "+f"((D)[1]), "+f"((D)[2]), "+f"((D)[3]) \
        : "r"(A0), "r"(A1), "r"(A2), "r"(A3), "r"(B0), "r"(B1))

__device__ __forceinline__ uint32_t pkh(float a, float b) {
    uint32_t r;
    asm("cvt.rn.f16x2.f32 %0, %1, %2;" : "=r"(r) : "f"(b), "f"(a));
    return r;
}
__device__ __forceinline__ void split2h(float a, float b, uint32_t& hi, uint32_t& lo) {
    hi = pkh(a, b);
    __half2 h = *reinterpret_cast<__half2*>(&hi);
    float2 f = __half22float2(h);
    lo = pkh(a - f.x, b - f.y);
}

// ---------------- small kernels -------------------------------------------
__global__ void init_kernel() {
    if (threadIdx.x < NSLOTS) { g_cnt[threadIdx.x] = 0; g_cur[threadIdx.x] = 0; }
}

__global__ void __launch_bounds__(256)
presplit_x(const float4* __restrict__ src, int n4)
{
    int i = blockIdx.x * 256 + threadIdx.x;
    if (i >= n4) return;
    float4 v = src[i];
    uint32_t h0, l0, h1, l1;
    split2h(v.x, v.y, h0, l0);
    split2h(v.z, v.w, h1, l1);
    ((uint2*)g_xh)[i] = make_uint2(h0, h1);
    ((uint2*)g_xl)[i] = make_uint2(l0, l1);
}

// weight fp32 -> fp16 (8 elems per thread)
__global__ void __launch_bounds__(256)
wconv(const float4* __restrict__ src, int code, int n8)
{
    int i = blockIdx.x * 256 + threadIdx.x;
    if (i >= n8) return;
    __half* dst;
    switch (code) {
        case 0: dst = g_tguh; break;
        case 1: dst = g_tdnh; break;
        case 2: dst = g_vguh; break;
        case 3: dst = g_vdnh; break;
        case 4: dst = g_sgh;  break;
        case 5: dst = g_suh;  break;
        default: dst = g_sdh; break;
    }
    float4 a = src[2*i], b = src[2*i + 1];
    ((uint4*)dst)[i] = make_uint4(pkh(a.x, a.y), pkh(a.z, a.w),
                                  pkh(b.x, b.y), pkh(b.z, b.w));
}

__global__ void __launch_bounds__(128)
router_kernel(const float* __restrict__ x, const int* __restrict__ tt,
              const float* __restrict__ tw, const float* __restrict__ tb,
              const float* __restrict__ vw, const float* __restrict__ vb,
              float* __restrict__ out_logits)
{
    int t = blockIdx.x;
    int tid = threadIdx.x;
    bool vis = (tt[t] != 0);
    const float* w = vis ? vw : tw;
    const float* b = vis ? vb : tb;

    __shared__ float xs[HID];
    __shared__ float lg[NEXP];
    const float* xr = x + (size_t)t * HID;
    for (int i = tid; i < HID; i += 128) xs[i] = xr[i];
    __syncthreads();

    int e = tid >> 3;
    int l = tid & 7;
    const float* we = w + (size_t)e * HID;
    float s = 0.f;
    for (int k = l; k < HID; k += 8) s += xs[k] * we[k];
    for (int o = 4; o; o >>= 1) s += __shfl_down_sync(0xffffffffu, s, o);
    if (l == 0) lg[e] = s;
    __syncthreads();

    if (tid < NEXP) out_logits[(size_t)t * NEXP + tid] = lg[tid];

    if (tid == 0) {
        float mx = lg[0];
        for (int i = 1; i < NEXP; i++) mx = fmaxf(mx, lg[i]);
        float p[NEXP]; float sum = 0.f;
        for (int i = 0; i < NEXP; i++) { p[i] = expf(lg[i] - mx); sum += p[i]; }
        float inv = 1.f / sum;
        float corr[NEXP];
        for (int i = 0; i < NEXP; i++) { p[i] *= inv; corr[i] = p[i] + b[i]; }

        bool used[NEXP];
        for (int i = 0; i < NEXP; i++) used[i] = false;
        int idxs[TOPK]; float ws[TOPK]; float wsum = 0.f;
        for (int j = 0; j < TOPK; j++) {
            int bi = -1; float bv = -1e30f;
            for (int i = 0; i < NEXP; i++)
                if (!used[i] && corr[i] > bv) { bv = corr[i]; bi = i; }
            used[bi] = true; idxs[j] = bi; ws[j] = p[bi]; wsum += p[bi];
        }
        float invw = 1.f / fmaxf(wsum, 1e-12f);
        int mbase = vis ? 16 : 0;
        for (int j = 0; j < TOPK; j++) {
            g_tope[t*TOPK + j] = mbase + idxs[j];
            g_topw[t*TOPK + j] = ws[j] * invw;
            atomicAdd(&g_cnt[mbase + idxs[j]], 1);
        }
    }
}

// scatter with fused scan
__global__ void scatter_kernel() {
    __shared__ int soff[NSLOTS];
    if (threadIdx.x == 0) {
        int acc = 0;
        for (int i = 0; i < NSLOTS; i++) { soff[i] = acc; acc += g_cnt[i]; }
    }
    __syncthreads();
    if (blockIdx.x == 0 && threadIdx.x < NSLOTS) g_off[threadIdx.x] = soff[threadIdx.x];
    int p = blockIdx.x * blockDim.x + threadIdx.x;
    if (p >= NPAIRS) return;
    int slot = g_tope[p];
    int pos = atomicAdd(&g_cur[slot], 1);
    int g = soff[slot] + pos;
    g_slot_tok[g] = p / TOPK;
    g_slot_w[g]   = g_topw[p];
    g_pair_row[p] = g;
}

// ---------------- fp16x2 split-precision GEMM, cp.async pipeline -----------
// C = (Ah+Al) @ B16 : 2 MMA passes. All operands fp16 in gmem.
// BM=128, BN=128, BK=32, 2-stage cp.async smem pipeline, 2 CTAs/SM.
#define STG_AH 0
#define STG_AL 10240
#define STG_B  20480
#define STG_SZ 29184
#define GEMM_SMEM (2*STG_SZ)

__global__ void __launch_bounds__(256, 2)
gemm_f16x2(int acode, int wcode, size_t bstride, int lda, int ldb, int ldc,
           int K, int mode, int slotbase, int scale, int cbuf, int coloff)
{
    extern __shared__ __align__(16) char S[];

    int M, baserow;
    if (mode == 2) { M = T_TOKENS; baserow = 0; }
    else { int s = slotbase + blockIdx.z; M = g_cnt[s]; baserow = g_off[s]; }
    int m0 = blockIdx.x * 128;
    if (m0 >= M) return;
    int n0 = blockIdx.y * 128;

    const __half *AHp, *ALp, *Bw;
    switch (acode) {
        case 0: AHp = g_xh;    ALp = g_xl;    break;
        case 1: AHp = g_hexph; ALp = g_hexpl; break;
        default: AHp = g_hshh; ALp = g_hshl;  break;
    }
    switch (wcode) {
        case 0: Bw = g_tguh; break;
        case 1: Bw = g_tdnh; break;
        case 2: Bw = g_vguh; break;
        case 3: Bw = g_vdnh; break;
        case 4: Bw = g_sgh;  break;
        case 5: Bw = g_suh;  break;
        default: Bw = g_sdh; break;
    }
    Bw += (size_t)blockIdx.z * bstride;

    float* Cb = ((cbuf == 0) ? g_cgu : (cbuf == 1) ? g_csh :
                 (cbuf == 2) ? g_oexp : g_osh) + coloff;

    int tid = threadIdx.x, lane = tid & 31, wid = tid >> 5;
    int wm = wid & 3, wn = wid >> 2;

    // --- cp.async loader mappings ---
    // A: 1024 16B-segments (2 planes x 128 rows x 4 segs), 4 per thread
    const __half* agm[4];
    uint32_t aoff[4];
    #pragma unroll
    for (int i = 0; i < 4; i++) {
        int s = tid + i * 256;
        int pl = s >> 9, r = (s >> 2) & 127, sg = s & 3;
        int rclamp = min(m0 + r, M - 1);
        size_t arow;
        if (mode == 0)      arow = (size_t)g_slot_tok[baserow + rclamp] * lda;
        else if (mode == 1) arow = (size_t)(baserow + rclamp) * lda;
        else                arow = (size_t)rclamp * lda;
        agm[i] = (pl ? ALp : AHp) + arow + sg * 8;
        aoff[i] = (pl ? STG_AL : STG_AH) + (uint32_t)r * 80u + (uint32_t)sg * 16u;
    }
    // B: 512 16B-segments (32 rows x 16 segs), 2 per thread
    const __half* bgm[2];
    uint32_t boff[2];
    #pragma unroll
    for (int i = 0; i < 2; i++) {
        int s = tid + i * 256;
        int r = s >> 4, cseg = s & 15;
        bgm[i] = Bw + (size_t)r * ldb + n0 + cseg * 8;
        boff[i] = STG_B + (uint32_t)r * 272u + (uint32_t)cseg * 16u;
    }

    float acc[2][8][4];
    #pragma unroll
    for (int i = 0; i < 2; i++)
        #pragma unroll
        for (int j = 0; j < 8; j++)
            #pragma unroll
            for (int q = 0; q < 4; q++) acc[i][j][q] = 0.f;

    uint32_t sbase = smem_u32(S);
    const int NCH = K / 32;

    // prologue: issue chunk 0 -> stage 0
    #pragma unroll
    for (int i = 0; i < 4; i++) cp_async16(sbase + aoff[i], agm[i]);
    #pragma unroll
    for (int i = 0; i < 2; i++) cp_async16(sbase + boff[i], bgm[i]);
    CP_COMMIT();
    #pragma unroll
    for (int i = 0; i < 4; i++) agm[i] += 32;
    #pragma unroll
    for (int i = 0; i < 2; i++) bgm[i] += (size_t)32 * ldb;

    for (int c = 0; c < NCH; c++) {
        int cur = c & 1;
        if (c + 1 < NCH) {
            uint32_t st = sbase + (cur ^ 1) * STG_SZ;
            #pragma unroll
            for (int i = 0; i < 4; i++) cp_async16(st + aoff[i], agm[i]);
            #pragma unroll
            for (int i = 0; i < 2; i++) cp_async16(st + boff[i], bgm[i]);
            CP_COMMIT();
            #pragma unroll
            for (int i = 0; i < 4; i++) agm[i] += 32;
            #pragma unroll
            for (int i = 0; i < 2; i++) bgm[i] += (size_t)32 * ldb;
            CP_WAIT(1);
        } else {
            CP_WAIT(0);
        }
        __syncthreads();

        uint32_t sb = sbase + (uint32_t)cur * STG_SZ;
        #pragma unroll
        for (int ks = 0; ks < 2; ks++) {
            uint32_t ah[2][4], al[2][4], b[8][2];
            #pragma unroll
            for (int mi = 0; mi < 2; mi++) {
                uint32_t ra = (uint32_t)(wm*32 + mi*16 + (lane & 15)) * 80u
                            + (uint32_t)(ks*32) + (uint32_t)((lane >> 4) * 16);
                LDSM4(ah[mi][0], ah[mi][1], ah[mi][2], ah[mi][3], sb + STG_AH + ra);
                LDSM4(al[mi][0], al[mi][1], al[mi][2], al[mi][3], sb + STG_AL + ra);
            }
            #pragma unroll
            for (int p = 0; p < 4; p++) {
                uint32_t rb = (uint32_t)(ks*16 + (lane & 15)) * 272u
                            + (uint32_t)((wn*64 + p*16 + ((lane >> 4) * 8)) * 2);
                LDSM4T(b[2*p][0], b[2*p][1], b[2*p+1][0], b[2*p+1][1], sb + STG_B + rb);
            }
            #pragma unroll
            for (int mi = 0; mi < 2; mi++)
                #pragma unroll
                for (int nj = 0; nj < 8; nj++) {
                    MMAF16(acc[mi][nj], ah[mi][0], ah[mi][1], ah[mi][2], ah[mi][3],
                           b[nj][0], b[nj][1]);
                    MMAF16(acc[mi][nj], al[mi][0], al[mi][1], al[mi][2], al[mi][3],
                           b[nj][0], b[nj][1]);
                }
        }
        __syncthreads();
    }

    // epilogue
    #pragma unroll
    for (int mi = 0; mi < 2; mi++) {
        int row0 = m0 + wm*32 + mi*16 + (lane >> 2);
        int row1 = row0 + 8;
        float w0 = 1.f, w1 = 1.f;
        if (scale) {
            if (row0 < M) w0 = g_slot_w[baserow + row0];
            if (row1 < M) w1 = g_slot_w[baserow + row1];
        }
        #pragma unroll
        for (int nj = 0; nj < 8; nj++) {
            int col = n0 + wn*64 + nj*8 + (lane & 3)*2;
            if (row0 < M) {
                float2 v = make_float2(acc[mi][nj][0]*w0, acc[mi][nj][1]*w0);
                *(float2*)(Cb + (size_t)(baserow + row0)*ldc + col) = v;
            }
            if (row1 < M) {
                float2 v = make_float2(acc[mi][nj][2]*w1, acc[mi][nj][3]*w1);
                *(float2*)(Cb + (size_t)(baserow + row1)*ldc + col) = v;
            }
        }
    }
}

// ---------------- elementwise SiLU * up -> fp16 hi/lo planes ---------------
__global__ void __launch_bounds__(256)
silu_experts()
{
    int row = blockIdx.y;
    int i = (blockIdx.x * 256 + threadIdx.x) * 2;
    int boundary = g_off[16];               // first vis row
    int I = (row < boundary) ? TI : VI;
    if (i >= I) return;
    const float* crow = g_cgu + (size_t)row * (2*TI);
    float ga = crow[i],     ua = crow[I + i];
    float gb = crow[i + 1], ub = crow[I + i + 1];
    float ha = ga / (1.f + __expf(-ga)) * ua;
    float hb = gb / (1.f + __expf(-gb)) * ub;
    uint32_t hi, lo;
    split2h(ha, hb, hi, lo);
    size_t o = (size_t)row * TI + i;
    *(uint32_t*)(g_hexph + o) = hi;
    *(uint32_t*)(g_hexpl + o) = lo;
}

__global__ void __launch_bounds__(256)
silu_shared()
{
    int row = blockIdx.y;
    int i = (blockIdx.x * 256 + threadIdx.x) * 2;
    const float* crow = g_csh + (size_t)row * (2*SI);
    float ga = crow[i],     ua = crow[SI + i];
    float gb = crow[i + 1], ub = crow[SI + i + 1];
    float ha = ga / (1.f + __expf(-ga)) * ua;
    float hb = gb / (1.f + __expf(-gb)) * ub;
    uint32_t hi, lo;
    split2h(ha, hb, hi, lo);
    size_t o = (size_t)row * SI + i;
    *(uint32_t*)(g_hshh + o) = hi;
    *(uint32_t*)(g_hshl + o) = lo;
}

// ---------------- finalize: gather 6 expert rows + shared ------------------
__global__ void __launch_bounds__(256)
finalize_kernel(float* __restrict__ out)
{
    int t = blockIdx.y;
    int h = blockIdx.x * 256 + threadIdx.x;
    float s = g_osh[(size_t)t * HID + h];
    #pragma unroll
    for (int j = 0; j < TOPK; j++) {
        int g = g_pair_row[t*TOPK + j];
        s += g_oexp[(size_t)g * HID + h];
    }
    out[(size_t)t * HID + h] = s;
}

// ---------------- launch ----------------------------------------------------
static inline void wc(const void* src, int code, size_t n) {
    int n8 = (int)(n / 8);
    wconv<<<(n8 + 255)/256, 256>>>((const float4*)src, code, n8);
}

extern "C" void kernel_launch(void* const* d_in, const int* in_sizes, int n_in,
                              void* d_out, int out_size)
{
    (void)in_sizes; (void)n_in; (void)out_size;
    const float* x   = (const float*)d_in[0];
    const int*   tt  = (const int*)  d_in[1];
    const float* trw = (const float*)d_in[2];
    const float* trb = (const float*)d_in[3];
    const float* tgu = (const float*)d_in[4];
    const float* tdn = (const float*)d_in[5];
    const float* vrw = (const float*)d_in[6];
    const float* vrb = (const float*)d_in[7];
    const float* vgu = (const float*)d_in[8];
    const float* vdn = (const float*)d_in[9];
    const float* sg  = (const float*)d_in[10];
    const float* su  = (const float*)d_in[11];
    const float* sd  = (const float*)d_in[12];
    float* out        = (float*)d_out;
    float* out_logits = out + (size_t)T_TOKENS * HID;

    cudaFuncSetAttribute(gemm_f16x2, cudaFuncAttributeMaxDynamicSharedMemorySize, GEMM_SMEM);

    presplit_x<<<(T_TOKENS*HID/4 + 255)/256, 256>>>((const float4*)x, T_TOKENS*HID/4); // 1
    wc(sg, 4, (size_t)HID*SI);                                                          // 2
    init_kernel<<<1, 32>>>();                                                           // 3
    wc(su, 5, (size_t)HID*SI);                                                          // 4
    wc(tgu, 0, (size_t)NEXP*HID*2*TI);                                                  // 5
    // 6: dense shared-gate GEMM — ncu profiled slot
    gemm_f16x2<<<dim3(32, SI/128, 1), 256, GEMM_SMEM>>>(
        0, 4, 0, HID, SI, 2*SI, HID, 2, 0, 0, 1, 0);
    router_kernel<<<T_TOKENS, 128>>>(x, tt, trw, trb, vrw, vrb, out_logits);            // 7
    gemm_f16x2<<<dim3(32, SI/128, 1), 256, GEMM_SMEM>>>(
        0, 5, 0, HID, SI, 2*SI, HID, 2, 0, 0, 1, SI);                                   // 8
    scatter_kernel<<<NPAIRS/256, 256>>>();                                              // 9

    // expert gate/up GEMMs
    gemm_f16x2<<<dim3(32, (2*TI)/128, 16), 256, GEMM_SMEM>>>(
        0, 0, (size_t)HID*2*TI, HID, 2*TI, 2*TI, HID, 0, 0,  0, 0, 0);
    wc(vgu, 2, (size_t)NEXP*HID*2*VI);
    gemm_f16x2<<<dim3(32, (2*VI)/128, 16), 256, GEMM_SMEM>>>(
        0, 2, (size_t)HID*2*VI, HID, 2*VI, 2*TI, HID, 0, 16, 0, 0, 0);

    silu_shared<<<dim3(SI/512, T_TOKENS), 256>>>();
    silu_experts<<<dim3(TI/512, NPAIRS), 256>>>();

    // down GEMMs
    wc(tdn, 1, (size_t)NEXP*TI*HID);
    gemm_f16x2<<<dim3(32, HID/128, 16), 256, GEMM_SMEM>>>(
        1, 1, (size_t)TI*HID, TI, HID, HID, TI, 1, 0,  1, 2, 0);
    wc(vdn, 3, (size_t)NEXP*VI*HID);
    gemm_f16x2<<<dim3(32, HID/128, 16), 256, GEMM_SMEM>>>(
        1, 3, (size_t)VI*HID, TI, HID, HID, VI, 1, 16, 1, 2, 0);
    wc(sd, 6, (size_t)SI*HID);
    gemm_f16x2<<<dim3(32, HID/128, 1), 256, GEMM_SMEM>>>(
        2, 6, 0, SI, HID, HID, SI, 2, 0, 0, 3, 0);

    finalize_kernel<<<dim3(HID/256, T_TOKENS), 256>>>(out);
}